// round 13
// baseline (speedup 1.0000x reference)
#include <cuda_runtime.h>
#include <cuda_bf16.h>
#include <cstdint>

typedef unsigned long long ull;

// Problem constants
#define TB   8
#define TT   20
#define TN   16
#define TC   1024
#define NPOS 2560          // B*T*N
#define NO   18            // 2*K2

// Scratch (allocation-free rule: __device__ globals)
// g_wTp layout: [rtap(18)][c2(512)][oh(2)][10 f2 (9 used + 1 pad)]
__device__ __align__(16) float2 g_wTp[18*512*2*10];
__device__ float g_offp[32*NPOS*18];           // 16 c-slices x 2 ratios
__device__ __nv_bfloat16 g_ahi[NPOS*TC];       // A hi (from gather)
__device__ __nv_bfloat16 g_alo[NPOS*TC];       // A lo
__device__ __nv_bfloat16 g_bhi[1024*1024];     // W hi
__device__ __nv_bfloat16 g_blo[1024*1024];     // W lo

__device__ __forceinline__ uint32_t smem_u32(const void* p) {
    uint32_t a;
    asm("{ .reg .u64 t; cvta.to.shared.u64 t, %1; cvt.u32.u64 %0, t; }"
        : "=r"(a) : "l"(p));
    return a;
}

// ---- packed fp32x2 helpers ------------------------------------------------
__device__ __forceinline__ void ffma2(ull& acc, ull a, ull b) {
    asm("fma.rn.f32x2 %0, %1, %2, %0;" : "+l"(acc) : "l"(a), "l"(b));
}
__device__ __forceinline__ float2 unpack2(ull v) {
    float2 r;
    asm("mov.b64 {%0, %1}, %2;" : "=f"(r.x), "=f"(r.y) : "l"(v));
    return r;
}
__device__ __forceinline__ ull lds64(uint32_t a) {
    ull v;
    asm volatile("ld.shared.b64 %0, [%1];" : "=l"(v) : "r"(a));
    return v;
}
__device__ __forceinline__ void lds128u64(ull& w0, ull& w1, uint32_t a) {
    asm volatile("ld.shared.v2.u64 {%0,%1}, [%2];" : "=l"(w0), "=l"(w1) : "r"(a));
}
__device__ __forceinline__ void cp_async8(uint32_t dst, const void* src) {
    asm volatile("cp.async.ca.shared.global [%0], [%1], 8;" :: "r"(dst), "l"(src));
}
__device__ __forceinline__ void cp_async16(uint32_t dst, const void* src) {
    asm volatile("cp.async.ca.shared.global [%0], [%1], 16;" :: "r"(dst), "l"(src));
}
#define CP_COMMIT() asm volatile("cp.async.commit_group;" ::: "memory")
#define CP_WAIT0()  asm volatile("cp.async.wait_group 0;" ::: "memory")

#define LDM4(r, addr) \
    asm volatile("ldmatrix.sync.aligned.m8n8.x4.shared.b16 {%0,%1,%2,%3}, [%4];" \
        : "=r"((r)[0]), "=r"((r)[1]), "=r"((r)[2]), "=r"((r)[3]) : "r"(addr))
#define LDM2(r, addr) \
    asm volatile("ldmatrix.sync.aligned.m8n8.x2.shared.b16 {%0,%1}, [%2];" \
        : "=r"((r)[0]), "=r"((r)[1]) : "r"(addr))

__device__ __forceinline__ void mma_bf16(float* d, const uint32_t* a, const uint32_t* b) {
    asm volatile("mma.sync.aligned.m16n8k16.row.col.f32.bf16.bf16.f32 "
                 "{%0,%1,%2,%3}, {%4,%5,%6,%7}, {%8,%9}, {%0,%1,%2,%3};"
                 : "+f"(d[0]), "+f"(d[1]), "+f"(d[2]), "+f"(d[3])
                 : "r"(a[0]), "r"(a[1]), "r"(a[2]), "r"(a[3]), "r"(b[0]), "r"(b[1]));
}

// ---------------------------------------------------------------------------
// Kernel 1: conv weight prep  p_w [18][1024][3][3] ->
//           g_wTp [rtap][c2][oh][10] f2 (pair over channels, oh = output half)
// ---------------------------------------------------------------------------
__global__ void k_wtrans(const float* __restrict__ w1, const float* __restrict__ w2) {
    int idx = blockIdx.x * 256 + threadIdx.x;
    if (idx >= 2*9*512*18) return;
    int o   = idx % 18;
    int c2  = (idx / 18) % 512;
    int tap = (idx / (18*512)) % 9;
    int r   = idx / (18*512*9);
    const float* w = r ? w2 : w1;
    float2 v;
    v.x = w[o*9216 + (2*c2)*9 + tap];
    v.y = w[o*9216 + (2*c2+1)*9 + tap];
    int oh = o / 9, oi = o - oh*9;
    g_wTp[(((r*9 + tap)*512 + c2)*2 + oh)*10 + oi] = v;
}

// ---------------------------------------------------------------------------
// Kernel 1b: W_hidden -> bf16 hi/lo split
// ---------------------------------------------------------------------------
union BPack { __nv_bfloat162 h2[2]; uint2 u; };

__global__ void k_wprep(const float* __restrict__ W) {
    int idx = blockIdx.x * 256 + threadIdx.x;     // one per 4 floats
    if (idx >= 1024*1024/4) return;
    float4 v = *(const float4*)(W + idx*4);
    BPack ph, pl;
    __nv_bfloat16 h;
    h = __float2bfloat16(v.x); ph.h2[0].x = h; pl.h2[0].x = __float2bfloat16(v.x - __bfloat162float(h));
    h = __float2bfloat16(v.y); ph.h2[0].y = h; pl.h2[0].y = __float2bfloat16(v.y - __bfloat162float(h));
    h = __float2bfloat16(v.z); ph.h2[1].x = h; pl.h2[1].x = __float2bfloat16(v.z - __bfloat162float(h));
    h = __float2bfloat16(v.w); ph.h2[1].y = h; pl.h2[1].y = __float2bfloat16(v.w - __bfloat162float(h));
    *(uint2*)(g_bhi + idx*4) = ph.u;
    *(uint2*)(g_blo + idx*4) = pl.u;
}

// ---------------------------------------------------------------------------
// Kernel 2: offset conv v4 — occ 3 (single wave) via halved accumulators.
// grid = (40 pos-tiles of 64) x (8 channel-eighths), block 256 = 8 warps.
// Warp = (ratio r, c-slice-half sh, output-half oh): acc[2 pos][9 out].
// X smem: [8 c2][160 rows] f2 (zero halo), cached loader slots.
// W smem: [18 rtap][2 oh][8 c2][10 f2] — 80B blocks, recomputed loader.
// ---------------------------------------------------------------------------
#define CV_XBUF 1280                 // f2
#define CV_WBUF 2880                 // f2: 18*2*8*10
#define CV_SMEM ((2*CV_XBUF + 2*CV_WBUF) * 8)   // 66560 B

__global__ void __launch_bounds__(256, 3) k_conv(const float* __restrict__ x) {
    extern __shared__ __align__(16) float2 cs[];
    const uint32_t sb  = smem_u32(cs);
    const uint32_t sX0 = sb;
    const uint32_t sX1 = sb + CV_XBUF*8;
    const uint32_t sW0 = sb + 2*CV_XBUF*8;
    const uint32_t sW1 = sW0 + CV_WBUF*8;

    const int tile = blockIdx.x;      // 0..39 = b*5 + tq
    const int e    = blockIdx.y;      // 0..7 channel-eighth
    const int b    = tile / 5;
    const int t0   = (tile - b*5) * 4;

    const int tid  = threadIdx.x;
    const int wid  = tid >> 5, lane = tid & 31;
    const int r    = wid >> 2;            // ratio index (0,1)
    const int sh   = (wid >> 1) & 1;      // c-slice half (4 c2)
    const int oh   = wid & 1;             // output half (9 outs)
    const int ratio = r + 1;
    const int tl = lane >> 4, nl = lane & 15;

    // zero X buffers once (halo slots never overwritten -> stay zero)
    for (int i = tid; i < 2*CV_XBUF; i += 256) cs[i] = make_float2(0.f, 0.f);

    // ---- X loader slots (cached; chunk advances src by ck*16B) ----
    uint32_t xoff[5], xdst[5];
    #pragma unroll
    for (int k = 0; k < 5; k++) {
        int idx = tid + k*256;
        int c2i = idx & 7, row = idx >> 3;
        int t = t0 + row/20 - 2, n = row%20 - 2;
        int c2 = e*64 + (c2i>>1)*16 + (c2i&1);
        xdst[k] = (uint32_t)((c2i*160 + row)*8);
        xoff[k] = (t >= 0 && t < TT && n >= 0 && n < TN)
                ? (uint32_t)((((b*TT + t)*TN + n)*TC + c2*2) * 4)
                : 0xFFFFFFFFu;
    }
    const char* xb = (const char*)x;
    const char* wb = (const char*)g_wTp;

    __syncthreads();   // zeros visible before async writes

    // W loader: 1440 ops/chunk (18 rtap x 2 oh x 8 c2 x 5), recomputed.
#define CV_ISSUE(ck, bX, bW) do { \
        _Pragma("unroll") \
        for (int k = 0; k < 5; k++) \
            if (xoff[k] != 0xFFFFFFFFu) \
                cp_async8((bX) + xdst[k], xb + xoff[k] + (uint32_t)(ck)*16u); \
        _Pragma("unroll") \
        for (int k = 0; k < 6; k++) { \
            int idx = tid + k*256; \
            if (idx < 1440) { \
                int q = idx % 5, rest = idx / 5; \
                int c2i = rest & 7, ohl = (rest >> 3) & 1, rtap = rest >> 4; \
                int c2 = e*64 + (c2i>>1)*16 + (c2i&1); \
                uint32_t dstb = (uint32_t)((((rtap*2 + ohl)*8 + c2i)*10) * 8); \
                size_t   srcb = ((size_t)(((rtap*512 + c2)*2 + ohl)*10)) * 8 \
                              + (size_t)(ck)*320u; \
                if (q < 4) cp_async16((bW) + dstb + q*16, wb + srcb + q*16); \
                else       cp_async8((bW) + dstb + 64,   wb + srcb + 64); \
            } \
        } \
        CP_COMMIT(); \
    } while (0)

    CV_ISSUE(0, sX0, sW0);

    ull acc[2][9];
    #pragma unroll
    for (int pp = 0; pp < 2; pp++)
        #pragma unroll
        for (int o = 0; o < 9; o++) acc[pp][o] = 0ULL;

    const int baserow = (tl + 2)*20 + nl + 2;

    for (int ck = 0; ck < 8; ck++) {
        const uint32_t bX = (ck & 1) ? sX1 : sX0;
        const uint32_t bW = (ck & 1) ? sW1 : sW0;
        CP_WAIT0();
        __syncthreads();
        if (ck < 7) CV_ISSUE(ck + 1, (ck & 1) ? sX0 : sX1, (ck & 1) ? sW0 : sW1);

        #pragma unroll
        for (int tap = 0; tap < 9; tap++) {
            const int dconst = (tap/3 - 1)*20 + (tap%3 - 1);
            const uint32_t xa = bX + (uint32_t)((baserow + dconst*ratio) * 8);
            const uint32_t wtap = bW + (uint32_t)(((r*9 + tap)*2 + oh) * 640);
            #pragma unroll
            for (int j = 0; j < 4; j++) {
                const uint32_t c2i = (uint32_t)(sh*4 + j);
                ull xp0 = lds64(xa + c2i*1280u);
                ull xp1 = lds64(xa + c2i*1280u + 320u);   // +2 t rows
                const uint32_t wc = wtap + c2i*80u;
                #pragma unroll
                for (int p2 = 0; p2 < 4; p2++) {
                    ull w0, w1;
                    lds128u64(w0, w1, wc + (uint32_t)(p2*16));
                    ffma2(acc[0][p2*2],   xp0, w0);
                    ffma2(acc[0][p2*2+1], xp0, w1);
                    ffma2(acc[1][p2*2],   xp1, w0);
                    ffma2(acc[1][p2*2+1], xp1, w1);
                }
                ull w8 = lds64(wc + 64u);
                ffma2(acc[0][8], xp0, w8);
                ffma2(acc[1][8], xp1, w8);
            }
        }
    }

    #pragma unroll
    for (int pp = 0; pp < 2; pp++) {
        int pos = b*320 + (t0 + tl + pp*2)*16 + nl;
        float* dst = g_offp + ((size_t)((e*2 + sh)*2 + r)*NPOS + pos)*18 + oh*9;
        #pragma unroll
        for (int o = 0; o < 9; o++) {
            float2 v = unpack2(acc[pp][o]);
            dst[o] = v.x + v.y;
        }
    }
#undef CV_ISSUE
}

// ---------------------------------------------------------------------------
// Kernel 3: deformable bilinear gather (R8 version; 16 partial slices now).
// ---------------------------------------------------------------------------
__global__ void __launch_bounds__(256) k_gather(const float* __restrict__ x,
                                                const float* __restrict__ b1,
                                                const float* __restrict__ b2,
                                                float* __restrict__ out_ftmad,
                                                int write_ftmad) {
    int pos = blockIdx.x;
    int bb  = pos / 320; int rem = pos - bb*320;
    int t   = rem >> 4,  n = rem & 15;

    __shared__ int   s_off[2][9][4];
    __shared__ float s_coe[2][9][4];

    int tid = threadIdx.x;
    if (tid < 18) {
        int r = tid / 9, k = tid - r*9;
        int ratio = r + 1;
        const float* bias = r ? b2 : b1;
        float offt = bias[k], offn = bias[k + 9];
        #pragma unroll
        for (int q = 0; q < 16; q++) {
            const float* op = g_offp + ((size_t)(q*2 + r)*NPOS + pos)*18;
            offt += op[k];
            offn += op[k + 9];
        }
        float Tp1 = (float)(TT + 2*ratio - 1);
        float Np1 = (float)(TN + 2*ratio - 1);
        float post = (float)(t + ratio) + (float)((k/3 - 1)*ratio) + offt;
        float posn = (float)(n + ratio) + (float)((k%3 - 1)*ratio) + offn;
        float flt = floorf(post), fln = floorf(posn);
        float ltt = fminf(fmaxf(flt,       0.f), Tp1);
        float ltn = fminf(fmaxf(fln,       0.f), Np1);
        float rbt = fminf(fmaxf(flt + 1.f, 0.f), Tp1);
        float rbn = fminf(fmaxf(fln + 1.f, 0.f), Np1);
        float pct = fminf(fmaxf(post, 0.f), Tp1);
        float pcn = fminf(fmaxf(posn, 0.f), Np1);
        float wltt = 1.f - fabsf(pct - ltt);
        float wrbt = 1.f - fabsf(pct - rbt);
        float wltn = 1.f - fabsf(pcn - ltn);
        float wrbn = 1.f - fabsf(pcn - rbn);
        s_coe[r][k][0] = wltt * wltn;
        s_coe[r][k][1] = wrbt * wrbn;
        s_coe[r][k][2] = wrbt * wltn;
        s_coe[r][k][3] = wltt * wrbn;
        int ict[4] = {(int)ltt, (int)rbt, (int)rbt, (int)ltt};
        int icn[4] = {(int)ltn, (int)rbn, (int)ltn, (int)rbn};
        #pragma unroll
        for (int q = 0; q < 4; q++) {
            int ts = ict[q] - ratio, ns = icn[q] - ratio;
            s_off[r][k][q] = ((unsigned)ts < (unsigned)TT && (unsigned)ns < (unsigned)TN)
                           ? ((bb*TT + ts)*TN + ns)*TC : -1;
        }
    }
    __syncthreads();

    int c = tid * 4;
    float dx = 0.f, dy = 0.f, dz = 0.f, dw = 0.f;
    #pragma unroll
    for (int r = 0; r < 2; r++) {
        #pragma unroll
        for (int k = 0; k < 9; k++) {
            float fx = 0.f, fy = 0.f, fz = 0.f, fw = 0.f;
            #pragma unroll
            for (int q = 0; q < 4; q++) {
                int   o   = s_off[r][k][q];
                float coe = s_coe[r][k][q];
                if (o >= 0) {
                    float4 v = *(const float4*)(x + o + c);
                    fx = fmaf(coe, v.x, fx);
                    fy = fmaf(coe, v.y, fy);
                    fz = fmaf(coe, v.z, fz);
                    fw = fmaf(coe, v.w, fw);
                }
            }
            if (r == 1 && write_ftmad) {
                float4 ov = make_float4(fx, fy, fz, fw);
                *(float4*)(out_ftmad + (pos*9 + k)*1024 + c) = ov;
            }
            dx += fx; dy += fy; dz += fz; dw += fw;
        }
    }
    const float s = 1.f / 18.f;
    float4 dv = make_float4(dx*s, dy*s, dz*s, dw*s);

    BPack ph, pl;
    __nv_bfloat16 h;
    h = __float2bfloat16(dv.x); ph.h2[0].x = h; pl.h2[0].x = __float2bfloat16(dv.x - __bfloat162float(h));
    h = __float2bfloat16(dv.y); ph.h2[0].y = h; pl.h2[0].y = __float2bfloat16(dv.y - __bfloat162float(h));
    h = __float2bfloat16(dv.z); ph.h2[1].x = h; pl.h2[1].x = __float2bfloat16(dv.z - __bfloat162float(h));
    h = __float2bfloat16(dv.w); ph.h2[1].y = h; pl.h2[1].y = __float2bfloat16(dv.w - __bfloat162float(h));
    *(uint2*)(g_ahi + (long)pos*1024 + c) = ph.u;
    *(uint2*)(g_alo + (long)pos*1024 + c) = pl.u;
}

// ---------------------------------------------------------------------------
// Kernel 4: HMMA split GEMM v1c (R12 — known-good): M128xN64, 320 CTAs,
// occ 2, cp.async double-buffered, 1 sync per slab.
// ---------------------------------------------------------------------------
#define KC       32
#define NSLAB    (1024/KC)
#define SA       80
#define S_AHI    0
#define S_ALO    (128*SA)
#define S_BHI    (2*128*SA)
#define S_BLO    (2*128*SA + 64*SA)
#define STG      (2*128*SA + 2*64*SA)
#define GSMEM    (2*STG)

__global__ void __launch_bounds__(256, 2) k_gemm_mma(float* __restrict__ out) {
    extern __shared__ __align__(16) char smem[];
    const uint32_t sb = smem_u32(smem);

    const int tid  = threadIdx.x;
    const int wid  = tid >> 5;
    const int lane = tid & 31;
    const int bx   = blockIdx.x;      // N tile of 64 (0..15)
    const int by   = blockIdx.y;      // M tile of 128 (0..19)
    const int wy   = wid & 3;
    const int wx   = wid >> 2;

    const __nv_bfloat16* pAhi = g_ahi + (size_t)by*128*1024;
    const __nv_bfloat16* pAlo = g_alo + (size_t)by*128*1024;
    const __nv_bfloat16* pBhi = g_bhi + (size_t)bx*64*1024;
    const __nv_bfloat16* pBlo = g_blo + (size_t)bx*64*1024;

    const int lrow = tid >> 2, lc4 = tid & 3;   // row 0..63, 16B chunk 0..3
    const size_t ga0 = (size_t)lrow*1024 + lc4*8;
    const size_t ga1 = (size_t)(lrow+64)*1024 + lc4*8;
    const uint32_t sa0 = (uint32_t)(lrow*SA + lc4*16);
    const uint32_t sa1 = (uint32_t)((lrow+64)*SA + lc4*16);

    float acc[2][4][4];
    #pragma unroll
    for (int i = 0; i < 2; i++)
        #pragma unroll
        for (int j = 0; j < 4; j++)
            #pragma unroll
            for (int q = 0; q < 4; q++) acc[i][j][q] = 0.f;

    const uint32_t laneA = (uint32_t)((lane & 15)*SA + (lane >> 4)*16);
    const uint32_t laneB = (uint32_t)((lane & 7)*SA + ((lane >> 3) & 1)*16);

#define GEMM_ISSUE(k0, bufbase) do { \
        cp_async16((bufbase) + S_AHI + sa0, pAhi + ga0 + (k0)); \
        cp_async16((bufbase) + S_AHI + sa1, pAhi + ga1 + (k0)); \
        cp_async16((bufbase) + S_ALO + sa0, pAlo + ga0 + (k0)); \
        cp_async16((bufbase) + S_ALO + sa1, pAlo + ga1 + (k0)); \
        cp_async16((bufbase) + S_BHI + sa0, pBhi + ga0 + (k0)); \
        cp_async16((bufbase) + S_BLO + sa0, pBlo + ga0 + (k0)); \
        CP_COMMIT(); \
    } while (0)

    GEMM_ISSUE(0, sb);

    for (int s = 0; s < NSLAB; s++) {
        const uint32_t base = sb + (uint32_t)(s & 1)*STG;
        CP_WAIT0();
        __syncthreads();
        if (s + 1 < NSLAB)
            GEMM_ISSUE((size_t)(s + 1)*KC, sb + (uint32_t)((s + 1) & 1)*STG);

        #pragma unroll
        for (int kk = 0; kk < 2; kk++) {
            uint32_t kB = kk * 32;
            uint32_t ah[2][4], al[2][4], bh[4][2], bl[4][2];
            #pragma unroll
            for (int mi = 0; mi < 2; mi++) {
                uint32_t moff = (uint32_t)((wy*32 + mi*16)*SA) + kB + laneA;
                LDM4(ah[mi], base + S_AHI + moff);
                LDM4(al[mi], base + S_ALO + moff);
            }
            #pragma unroll
            for (int ni = 0; ni < 4; ni++) {
                uint32_t noff = (uint32_t)((wx*32 + ni*8)*SA) + kB + laneB;
                LDM2(bh[ni], base + S_BHI + noff);
                LDM2(bl[ni], base + S_BLO + noff);
            }
            #pragma unroll
            for (int mi = 0; mi < 2; mi++)
                #pragma unroll
                for (int ni = 0; ni < 4; ni++) {
                    mma_bf16(acc[mi][ni], ah[mi], bh[ni]);
                    mma_bf16(acc[mi][ni], ah[mi], bl[ni]);
                    mma_bf16(acc[mi][ni], al[mi], bh[ni]);
                }
        }
    }
#undef GEMM_ISSUE

    const int r0 = (lane >> 2);
    const int c0 = (lane & 3) * 2;
    #pragma unroll
    for (int mi = 0; mi < 2; mi++) {
        #pragma unroll
        for (int ni = 0; ni < 4; ni++) {
            size_t row = (size_t)by*128 + wy*32 + mi*16 + r0;
            size_t col = (size_t)bx*64 + wx*32 + ni*8 + c0;
            *(float2*)(out + row*1024 + col)       = make_float2(acc[mi][ni][0], acc[mi][ni][1]);
            *(float2*)(out + (row + 8)*1024 + col) = make_float2(acc[mi][ni][2], acc[mi][ni][3]);
        }
    }
}

// ---------------------------------------------------------------------------
extern "C" void kernel_launch(void* const* d_in, const int* in_sizes, int n_in,
                              void* d_out, int out_size) {
    const float* xf  = (const float*)d_in[0];  // person_features [8,20,16,1024]
    const float* Wh  = (const float*)d_in[1];  // W_hidden [1024,1024]
    const float* w1  = (const float*)d_in[2];  // p_w1 [18,1024,3,3]
    const float* bb1 = (const float*)d_in[3];  // p_b1 [18]
    const float* w2  = (const float*)d_in[4];  // p_w2 [18,1024,3,3]
    const float* bb2 = (const float*)d_in[5];  // p_b2 [18]
    (void)in_sizes; (void)n_in;

    float* out       = (float*)d_out;
    float* out_dyn   = out;                       // [2560,1024]
    float* out_ftmad = out + (long)NPOS * TC;     // [2560,9,1024]
    int write_ftmad  = (out_size >= NPOS*TC + NPOS*9*TC) ? 1 : 0;

    cudaFuncSetAttribute(k_gemm_mma, cudaFuncAttributeMaxDynamicSharedMemorySize,
                         GSMEM);
    cudaFuncSetAttribute(k_conv, cudaFuncAttributeMaxDynamicSharedMemorySize,
                         CV_SMEM);

    k_wtrans<<<(2*9*512*18 + 255)/256, 256>>>(w1, w2);
    k_wprep<<<1024, 256>>>(Wh);

    dim3 gconv(40, 8);
    k_conv<<<gconv, 256, CV_SMEM>>>(xf);

    k_gather<<<NPOS, 256>>>(xf, bb1, bb2, out_ftmad, write_ftmad);

    dim3 ggemm(16, 20);
    k_gemm_mma<<<ggemm, 256, GSMEM>>>(out_dyn);
}

// round 14
// speedup vs baseline: 1.0074x; 1.0074x over previous
#include <cuda_runtime.h>
#include <cuda_bf16.h>
#include <cstdint>

typedef unsigned long long ull;

// Problem constants
#define TB   8
#define TT   20
#define TN   16
#define TC   1024
#define NPOS 2560          // B*T*N
#define NO   18            // 2*K2

// Scratch (allocation-free rule: __device__ globals)
__device__ __align__(16) float2 g_wTp[2*9*512*18];  // conv weights, channel-paired
__device__ float g_offp[64*NPOS*18];           // conv partials: 32 c-slices x 2 ratios
__device__ __nv_bfloat16 g_ahi[NPOS*TC];       // A hi (from gather)
__device__ __nv_bfloat16 g_alo[NPOS*TC];       // A lo
__device__ __nv_bfloat16 g_bhi[1024*1024];     // W hi
__device__ __nv_bfloat16 g_blo[1024*1024];     // W lo

__device__ __forceinline__ uint32_t smem_u32(const void* p) {
    uint32_t a;
    asm("{ .reg .u64 t; cvta.to.shared.u64 t, %1; cvt.u32.u64 %0, t; }"
        : "=r"(a) : "l"(p));
    return a;
}

// ---- packed fp32x2 helpers ------------------------------------------------
__device__ __forceinline__ void ffma2(ull& acc, ull a, ull b) {
    asm("fma.rn.f32x2 %0, %1, %2, %0;" : "+l"(acc) : "l"(a), "l"(b));
}
__device__ __forceinline__ float2 unpack2(ull v) {
    float2 r;
    asm("mov.b64 {%0, %1}, %2;" : "=f"(r.x), "=f"(r.y) : "l"(v));
    return r;
}
__device__ __forceinline__ ull lds64(uint32_t a) {
    ull v;
    asm volatile("ld.shared.b64 %0, [%1];" : "=l"(v) : "r"(a));
    return v;
}
__device__ __forceinline__ void lds128u64(ull& w0, ull& w1, uint32_t a) {
    asm volatile("ld.shared.v2.u64 {%0,%1}, [%2];" : "=l"(w0), "=l"(w1) : "r"(a));
}
__device__ __forceinline__ void cp_async8(uint32_t dst, const void* src) {
    asm volatile("cp.async.ca.shared.global [%0], [%1], 8;" :: "r"(dst), "l"(src));
}
__device__ __forceinline__ void cp_async16(uint32_t dst, const void* src) {
    asm volatile("cp.async.ca.shared.global [%0], [%1], 16;" :: "r"(dst), "l"(src));
}
#define CP_COMMIT() asm volatile("cp.async.commit_group;" ::: "memory")
#define CP_WAIT0()  asm volatile("cp.async.wait_group 0;" ::: "memory")

#define LDM4(r, addr) \
    asm volatile("ldmatrix.sync.aligned.m8n8.x4.shared.b16 {%0,%1,%2,%3}, [%4];" \
        : "=r"((r)[0]), "=r"((r)[1]), "=r"((r)[2]), "=r"((r)[3]) : "r"(addr))
#define LDM2(r, addr) \
    asm volatile("ldmatrix.sync.aligned.m8n8.x2.shared.b16 {%0,%1}, [%2];" \
        : "=r"((r)[0]), "=r"((r)[1]) : "r"(addr))

__device__ __forceinline__ void mma_bf16(float* d, const uint32_t* a, const uint32_t* b) {
    asm volatile("mma.sync.aligned.m16n8k16.row.col.f32.bf16.bf16.f32 "
                 "{%0,%1,%2,%3}, {%4,%5,%6,%7}, {%8,%9}, {%0,%1,%2,%3};"
                 : "+f"(d[0]), "+f"(d[1]), "+f"(d[2]), "+f"(d[3])
                 : "r"(a[0]), "r"(a[1]), "r"(a[2]), "r"(a[3]), "r"(b[0]), "r"(b[1]));
}

// ---------------------------------------------------------------------------
// Kernel 1: conv weight prep  p_w [18][1024][3][3] -> g_wTp [rtap][c2][18] f2
// ---------------------------------------------------------------------------
__global__ void k_wtrans(const float* __restrict__ w1, const float* __restrict__ w2) {
    int idx = blockIdx.x * 256 + threadIdx.x;
    if (idx >= 2*9*512*18) return;
    int o   = idx % 18;
    int c2  = (idx / 18) % 512;
    int tap = (idx / (18*512)) % 9;
    int r   = idx / (18*512*9);
    const float* w = r ? w2 : w1;
    float2 v;
    v.x = w[o*9216 + (2*c2)*9 + tap];
    v.y = w[o*9216 + (2*c2+1)*9 + tap];
    g_wTp[idx] = v;
}

// ---------------------------------------------------------------------------
// Kernel 1b: W_hidden -> bf16 hi/lo split
// ---------------------------------------------------------------------------
union BPack { __nv_bfloat162 h2[2]; uint2 u; };

__global__ void k_wprep(const float* __restrict__ W) {
    int idx = blockIdx.x * 256 + threadIdx.x;     // one per 4 floats
    if (idx >= 1024*1024/4) return;
    float4 v = *(const float4*)(W + idx*4);
    BPack ph, pl;
    __nv_bfloat16 h;
    h = __float2bfloat16(v.x); ph.h2[0].x = h; pl.h2[0].x = __float2bfloat16(v.x - __bfloat162float(h));
    h = __float2bfloat16(v.y); ph.h2[0].y = h; pl.h2[0].y = __float2bfloat16(v.y - __bfloat162float(h));
    h = __float2bfloat16(v.z); ph.h2[1].x = h; pl.h2[1].x = __float2bfloat16(v.z - __bfloat162float(h));
    h = __float2bfloat16(v.w); ph.h2[1].y = h; pl.h2[1].y = __float2bfloat16(v.w - __bfloat162float(h));
    *(uint2*)(g_bhi + idx*4) = ph.u;
    *(uint2*)(g_blo + idx*4) = pl.u;
}

// ---------------------------------------------------------------------------
// Kernel 2: offset conv v3 (R12 version, occ 2 — known-good).
// grid = (40 pos-tiles of 64) x (8 channel-eighths of 64 c2), block 256.
// ---------------------------------------------------------------------------
#define CV_XBUF 1280                 // f2: 8 c2 * 160 rows
#define CV_WBUF 2592                 // f2: 18 * 8 * 18
#define CV_SMEM ((2*CV_XBUF + 2*CV_WBUF) * 8)   // 61952 B

__global__ void __launch_bounds__(256, 2) k_conv(const float* __restrict__ x) {
    extern __shared__ __align__(16) float2 cs[];
    const uint32_t sb  = smem_u32(cs);
    const uint32_t sX0 = sb;
    const uint32_t sX1 = sb + CV_XBUF*8;
    const uint32_t sW0 = sb + 2*CV_XBUF*8;
    const uint32_t sW1 = sW0 + CV_WBUF*8;

    const int tile = blockIdx.x;      // 0..39 = b*5 + tq
    const int e    = blockIdx.y;      // 0..7 channel-eighth
    const int b    = tile / 5;
    const int t0   = (tile - b*5) * 4;

    const int tid  = threadIdx.x;
    const int wid  = tid >> 5, lane = tid & 31;
    const int r    = wid >> 2;        // ratio index (0,1)
    const int s    = wid & 3;         // c-slice within eighth
    const int ratio = r + 1;
    const int tl = lane >> 4, nl = lane & 15;

    // zero X buffers once (halo slots never overwritten -> stay zero)
    for (int i = tid; i < 2*CV_XBUF; i += 256) cs[i] = make_float2(0.f, 0.f);

    // ---- loader slots (chunk ck advances src by fixed byte step) ----
    uint32_t xoff[5], xdst[5];
    #pragma unroll
    for (int k = 0; k < 5; k++) {
        int idx = tid + k*256;
        int c2i = idx & 7, row = idx >> 3;
        int t = t0 + row/20 - 2, n = row%20 - 2;
        int c2 = e*64 + (c2i>>1)*16 + (c2i&1);
        xdst[k] = (uint32_t)((c2i*160 + row)*8);
        xoff[k] = (t >= 0 && t < TT && n >= 0 && n < TN)
                ? (uint32_t)((((b*TT + t)*TN + n)*TC + c2*2) * 4)
                : 0xFFFFFFFFu;
    }
    uint32_t woff[6], wdst[6];
    #pragma unroll
    for (int k = 0; k < 6; k++) {
        int idx = tid + k*256;
        if (idx < 1296) {
            int o2 = idx % 9, c2i = (idx/9) & 7, rtap = idx / 72;
            int c2 = e*64 + (c2i>>1)*16 + (c2i&1);
            wdst[k] = (uint32_t)((((rtap*8 + c2i)*18) + o2*2) * 8);
            woff[k] = (uint32_t)((((rtap*512 + c2)*18) + o2*2) * 8);
        } else woff[k] = 0xFFFFFFFFu;
    }
    const char* xb = (const char*)x;
    const char* wb = (const char*)g_wTp;

    __syncthreads();   // zeros visible before async writes

#define CV_ISSUE(ck, bX, bW) do { \
        _Pragma("unroll") \
        for (int k = 0; k < 5; k++) \
            if (xoff[k] != 0xFFFFFFFFu) \
                cp_async8((bX) + xdst[k], xb + xoff[k] + (uint32_t)(ck)*16u); \
        _Pragma("unroll") \
        for (int k = 0; k < 6; k++) \
            if (woff[k] != 0xFFFFFFFFu) \
                cp_async16((bW) + wdst[k], wb + woff[k] + (uint32_t)(ck)*288u); \
        CP_COMMIT(); \
    } while (0)

    CV_ISSUE(0, sX0, sW0);

    ull acc[2][18];
    #pragma unroll
    for (int pp = 0; pp < 2; pp++)
        #pragma unroll
        for (int o = 0; o < 18; o++) acc[pp][o] = 0ULL;

    const int baserow = (tl + 2)*20 + nl + 2;

    for (int ck = 0; ck < 8; ck++) {
        const uint32_t bX = (ck & 1) ? sX1 : sX0;
        const uint32_t bW = (ck & 1) ? sW1 : sW0;
        CP_WAIT0();
        __syncthreads();
        if (ck < 7) CV_ISSUE(ck + 1, (ck & 1) ? sX0 : sX1, (ck & 1) ? sW0 : sW1);

        #pragma unroll
        for (int tap = 0; tap < 9; tap++) {
            const int dconst = (tap/3 - 1)*20 + (tap%3 - 1);
            const uint32_t xa = bX + (uint32_t)((baserow + dconst*ratio) * 8);
            const uint32_t wa = bW + (uint32_t)((r*9 + tap) * 1152);
            #pragma unroll
            for (int j = 0; j < 2; j++) {
                const uint32_t c2i = (uint32_t)(s*2 + j);
                ull xp0 = lds64(xa + c2i*1280u);
                ull xp1 = lds64(xa + c2i*1280u + 320u);   // +2 t rows
                const uint32_t wc = wa + c2i*144u;
                #pragma unroll
                for (int op = 0; op < 9; op++) {
                    ull w0, w1;
                    lds128u64(w0, w1, wc + (uint32_t)(op*16));
                    ffma2(acc[0][op*2],   xp0, w0);
                    ffma2(acc[0][op*2+1], xp0, w1);
                    ffma2(acc[1][op*2],   xp1, w0);
                    ffma2(acc[1][op*2+1], xp1, w1);
                }
            }
        }
    }

    #pragma unroll
    for (int pp = 0; pp < 2; pp++) {
        int pos = b*320 + (t0 + tl + pp*2)*16 + nl;
        float* dst = g_offp + ((size_t)((e*4 + s)*2 + r)*NPOS + pos)*18;
        #pragma unroll
        for (int o = 0; o < 18; o++) {
            float2 v = unpack2(acc[pp][o]);
            dst[o] = v.x + v.y;
        }
    }
#undef CV_ISSUE
}

// ---------------------------------------------------------------------------
// Kernel 3: deformable bilinear gather — branch-free corner loads.
// Invalid corners get off=0 (safe row) and coe=0: contribution is exactly 0,
// all 72 float4 loads become unconditional -> full load batching (MLP).
// ---------------------------------------------------------------------------
__global__ void __launch_bounds__(256) k_gather(const float* __restrict__ x,
                                                const float* __restrict__ b1,
                                                const float* __restrict__ b2,
                                                float* __restrict__ out_ftmad,
                                                int write_ftmad) {
    int pos = blockIdx.x;
    int bb  = pos / 320; int rem = pos - bb*320;
    int t   = rem >> 4,  n = rem & 15;

    __shared__ int   s_off[2][9][4];
    __shared__ float s_coe[2][9][4];

    int tid = threadIdx.x;
    if (tid < 18) {
        int r = tid / 9, k = tid - r*9;
        int ratio = r + 1;
        const float* bias = r ? b2 : b1;
        float offt = bias[k], offn = bias[k + 9];
        #pragma unroll
        for (int q = 0; q < 32; q++) {
            const float* op = g_offp + ((size_t)(q*2 + r)*NPOS + pos)*18;
            offt += op[k];
            offn += op[k + 9];
        }
        float Tp1 = (float)(TT + 2*ratio - 1);
        float Np1 = (float)(TN + 2*ratio - 1);
        float post = (float)(t + ratio) + (float)((k/3 - 1)*ratio) + offt;
        float posn = (float)(n + ratio) + (float)((k%3 - 1)*ratio) + offn;
        float flt = floorf(post), fln = floorf(posn);
        float ltt = fminf(fmaxf(flt,       0.f), Tp1);
        float ltn = fminf(fmaxf(fln,       0.f), Np1);
        float rbt = fminf(fmaxf(flt + 1.f, 0.f), Tp1);
        float rbn = fminf(fmaxf(fln + 1.f, 0.f), Np1);
        float pct = fminf(fmaxf(post, 0.f), Tp1);
        float pcn = fminf(fmaxf(posn, 0.f), Np1);
        float wltt = 1.f - fabsf(pct - ltt);
        float wrbt = 1.f - fabsf(pct - rbt);
        float wltn = 1.f - fabsf(pcn - ltn);
        float wrbn = 1.f - fabsf(pcn - rbn);
        float coe[4];
        coe[0] = wltt * wltn;   // lt
        coe[1] = wrbt * wrbn;   // rb
        coe[2] = wrbt * wltn;   // lb
        coe[3] = wltt * wrbn;   // rt
        int ict[4] = {(int)ltt, (int)rbt, (int)rbt, (int)ltt};
        int icn[4] = {(int)ltn, (int)rbn, (int)ltn, (int)rbn};
        #pragma unroll
        for (int q = 0; q < 4; q++) {
            int ts = ict[q] - ratio, ns = icn[q] - ratio;
            bool valid = ((unsigned)ts < (unsigned)TT && (unsigned)ns < (unsigned)TN);
            s_off[r][k][q] = valid ? ((bb*TT + ts)*TN + ns)*TC : 0;
            s_coe[r][k][q] = valid ? coe[q] : 0.f;
        }
    }
    __syncthreads();

    int c = tid * 4;
    float dx = 0.f, dy = 0.f, dz = 0.f, dw = 0.f;
    #pragma unroll
    for (int r = 0; r < 2; r++) {
        #pragma unroll
        for (int k = 0; k < 9; k++) {
            float fx = 0.f, fy = 0.f, fz = 0.f, fw = 0.f;
            #pragma unroll
            for (int q = 0; q < 4; q++) {
                float coe = s_coe[r][k][q];
                float4 v = *(const float4*)(x + s_off[r][k][q] + c);
                fx = fmaf(coe, v.x, fx);
                fy = fmaf(coe, v.y, fy);
                fz = fmaf(coe, v.z, fz);
                fw = fmaf(coe, v.w, fw);
            }
            if (r == 1 && write_ftmad) {
                float4 ov = make_float4(fx, fy, fz, fw);
                *(float4*)(out_ftmad + (pos*9 + k)*1024 + c) = ov;
            }
            dx += fx; dy += fy; dz += fz; dw += fw;
        }
    }
    const float s = 1.f / 18.f;
    float4 dv = make_float4(dx*s, dy*s, dz*s, dw*s);

    BPack ph, pl;
    __nv_bfloat16 h;
    h = __float2bfloat16(dv.x); ph.h2[0].x = h; pl.h2[0].x = __float2bfloat16(dv.x - __bfloat162float(h));
    h = __float2bfloat16(dv.y); ph.h2[0].y = h; pl.h2[0].y = __float2bfloat16(dv.y - __bfloat162float(h));
    h = __float2bfloat16(dv.z); ph.h2[1].x = h; pl.h2[1].x = __float2bfloat16(dv.z - __bfloat162float(h));
    h = __float2bfloat16(dv.w); ph.h2[1].y = h; pl.h2[1].y = __float2bfloat16(dv.w - __bfloat162float(h));
    *(uint2*)(g_ahi + (long)pos*1024 + c) = ph.u;
    *(uint2*)(g_alo + (long)pos*1024 + c) = pl.u;
}

// ---------------------------------------------------------------------------
// Kernel 4: HMMA split GEMM v1c (R12 — known-good): M128xN64, 320 CTAs,
// occ 2, cp.async double-buffered, 1 sync per slab.
// ---------------------------------------------------------------------------
#define KC       32
#define NSLAB    (1024/KC)
#define SA       80
#define S_AHI    0
#define S_ALO    (128*SA)
#define S_BHI    (2*128*SA)
#define S_BLO    (2*128*SA + 64*SA)
#define STG      (2*128*SA + 2*64*SA)
#define GSMEM    (2*STG)

__global__ void __launch_bounds__(256, 2) k_gemm_mma(float* __restrict__ out) {
    extern __shared__ __align__(16) char smem[];
    const uint32_t sb = smem_u32(smem);

    const int tid  = threadIdx.x;
    const int wid  = tid >> 5;
    const int lane = tid & 31;
    const int bx   = blockIdx.x;      // N tile of 64 (0..15)
    const int by   = blockIdx.y;      // M tile of 128 (0..19)
    const int wy   = wid & 3;
    const int wx   = wid >> 2;

    const __nv_bfloat16* pAhi = g_ahi + (size_t)by*128*1024;
    const __nv_bfloat16* pAlo = g_alo + (size_t)by*128*1024;
    const __nv_bfloat16* pBhi = g_bhi + (size_t)bx*64*1024;
    const __nv_bfloat16* pBlo = g_blo + (size_t)bx*64*1024;

    const int lrow = tid >> 2, lc4 = tid & 3;   // row 0..63, 16B chunk 0..3
    const size_t ga0 = (size_t)lrow*1024 + lc4*8;
    const size_t ga1 = (size_t)(lrow+64)*1024 + lc4*8;
    const uint32_t sa0 = (uint32_t)(lrow*SA + lc4*16);
    const uint32_t sa1 = (uint32_t)((lrow+64)*SA + lc4*16);

    float acc[2][4][4];
    #pragma unroll
    for (int i = 0; i < 2; i++)
        #pragma unroll
        for (int j = 0; j < 4; j++)
            #pragma unroll
            for (int q = 0; q < 4; q++) acc[i][j][q] = 0.f;

    const uint32_t laneA = (uint32_t)((lane & 15)*SA + (lane >> 4)*16);
    const uint32_t laneB = (uint32_t)((lane & 7)*SA + ((lane >> 3) & 1)*16);

#define GEMM_ISSUE(k0, bufbase) do { \
        cp_async16((bufbase) + S_AHI + sa0, pAhi + ga0 + (k0)); \
        cp_async16((bufbase) + S_AHI + sa1, pAhi + ga1 + (k0)); \
        cp_async16((bufbase) + S_ALO + sa0, pAlo + ga0 + (k0)); \
        cp_async16((bufbase) + S_ALO + sa1, pAlo + ga1 + (k0)); \
        cp_async16((bufbase) + S_BHI + sa0, pBhi + ga0 + (k0)); \
        cp_async16((bufbase) + S_BLO + sa0, pBlo + ga0 + (k0)); \
        CP_COMMIT(); \
    } while (0)

    GEMM_ISSUE(0, sb);

    for (int s = 0; s < NSLAB; s++) {
        const uint32_t base = sb + (uint32_t)(s & 1)*STG;
        CP_WAIT0();
        __syncthreads();
        if (s + 1 < NSLAB)
            GEMM_ISSUE((size_t)(s + 1)*KC, sb + (uint32_t)((s + 1) & 1)*STG);

        #pragma unroll
        for (int kk = 0; kk < 2; kk++) {
            uint32_t kB = kk * 32;
            uint32_t ah[2][4], al[2][4], bh[4][2], bl[4][2];
            #pragma unroll
            for (int mi = 0; mi < 2; mi++) {
                uint32_t moff = (uint32_t)((wy*32 + mi*16)*SA) + kB + laneA;
                LDM4(ah[mi], base + S_AHI + moff);
                LDM4(al[mi], base + S_ALO + moff);
            }
            #pragma unroll
            for (int ni = 0; ni < 4; ni++) {
                uint32_t noff = (uint32_t)((wx*32 + ni*8)*SA) + kB + laneB;
                LDM2(bh[ni], base + S_BHI + noff);
                LDM2(bl[ni], base + S_BLO + noff);
            }
            #pragma unroll
            for (int mi = 0; mi < 2; mi++)
                #pragma unroll
                for (int ni = 0; ni < 4; ni++) {
                    mma_bf16(acc[mi][ni], ah[mi], bh[ni]);
                    mma_bf16(acc[mi][ni], ah[mi], bl[ni]);
                    mma_bf16(acc[mi][ni], al[mi], bh[ni]);
                }
        }
    }
#undef GEMM_ISSUE

    const int r0 = (lane >> 2);
    const int c0 = (lane & 3) * 2;
    #pragma unroll
    for (int mi = 0; mi < 2; mi++) {
        #pragma unroll
        for (int ni = 0; ni < 4; ni++) {
            size_t row = (size_t)by*128 + wy*32 + mi*16 + r0;
            size_t col = (size_t)bx*64 + wx*32 + ni*8 + c0;
            *(float2*)(out + row*1024 + col)       = make_float2(acc[mi][ni][0], acc[mi][ni][1]);
            *(float2*)(out + (row + 8)*1024 + col) = make_float2(acc[mi][ni][2], acc[mi][ni][3]);
        }
    }
}

// ---------------------------------------------------------------------------
extern "C" void kernel_launch(void* const* d_in, const int* in_sizes, int n_in,
                              void* d_out, int out_size) {
    const float* xf  = (const float*)d_in[0];  // person_features [8,20,16,1024]
    const float* Wh  = (const float*)d_in[1];  // W_hidden [1024,1024]
    const float* w1  = (const float*)d_in[2];  // p_w1 [18,1024,3,3]
    const float* bb1 = (const float*)d_in[3];  // p_b1 [18]
    const float* w2  = (const float*)d_in[4];  // p_w2 [18,1024,3,3]
    const float* bb2 = (const float*)d_in[5];  // p_b2 [18]
    (void)in_sizes; (void)n_in;

    float* out       = (float*)d_out;
    float* out_dyn   = out;                       // [2560,1024]
    float* out_ftmad = out + (long)NPOS * TC;     // [2560,9,1024]
    int write_ftmad  = (out_size >= NPOS*TC + NPOS*9*TC) ? 1 : 0;

    cudaFuncSetAttribute(k_gemm_mma, cudaFuncAttributeMaxDynamicSharedMemorySize,
                         GSMEM);
    cudaFuncSetAttribute(k_conv, cudaFuncAttributeMaxDynamicSharedMemorySize,
                         CV_SMEM);

    k_wtrans<<<(2*9*512*18 + 255)/256, 256>>>(w1, w2);
    k_wprep<<<1024, 256>>>(Wh);

    dim3 gconv(40, 8);
    k_conv<<<gconv, 256, CV_SMEM>>>(xf);

    k_gather<<<NPOS, 256>>>(xf, bb1, bb2, out_ftmad, write_ftmad);

    dim3 ggemm(16, 20);
    k_gemm_mma<<<ggemm, 256, GSMEM>>>(out_dyn);
}

// round 15
// speedup vs baseline: 1.1211x; 1.1129x over previous
#include <cuda_runtime.h>
#include <cuda_bf16.h>
#include <cstdint>

typedef unsigned long long ull;

// Problem constants
#define TB   8
#define TT   20
#define TN   16
#define TC   1024
#define NPOS 2560          // B*T*N
#define NO   18            // 2*K2

// Scratch (allocation-free rule: __device__ globals)
__device__ float g_offp[16*NPOS*18];           // conv partials: 8 eighths x 2 ratios
__device__ __nv_bfloat16 g_xhi[NPOS*TC];       // X hi (for tensor conv)
__device__ __nv_bfloat16 g_xlo[NPOS*TC];       // X lo
__device__ __nv_bfloat16 g_cwhi[2*9*24*1024];  // conv W hi [r][tap][24 o(pad)][c]
__device__ __nv_bfloat16 g_cwlo[2*9*24*1024];  // conv W lo
__device__ __nv_bfloat16 g_ahi[NPOS*TC];       // A hi (from gather)
__device__ __nv_bfloat16 g_alo[NPOS*TC];       // A lo
__device__ __nv_bfloat16 g_bhi[1024*1024];     // W_hidden hi
__device__ __nv_bfloat16 g_blo[1024*1024];     // W_hidden lo

__device__ __forceinline__ uint32_t smem_u32(const void* p) {
    uint32_t a;
    asm("{ .reg .u64 t; cvta.to.shared.u64 t, %1; cvt.u32.u64 %0, t; }"
        : "=r"(a) : "l"(p));
    return a;
}
__device__ __forceinline__ void cp_async16(uint32_t dst, const void* src) {
    asm volatile("cp.async.ca.shared.global [%0], [%1], 16;" :: "r"(dst), "l"(src));
}
#define CP_COMMIT() asm volatile("cp.async.commit_group;" ::: "memory")
#define CP_WAIT0()  asm volatile("cp.async.wait_group 0;" ::: "memory")

#define LDM4(r, addr) \
    asm volatile("ldmatrix.sync.aligned.m8n8.x4.shared.b16 {%0,%1,%2,%3}, [%4];" \
        : "=r"((r)[0]), "=r"((r)[1]), "=r"((r)[2]), "=r"((r)[3]) : "r"(addr))
#define LDM2(r, addr) \
    asm volatile("ldmatrix.sync.aligned.m8n8.x2.shared.b16 {%0,%1}, [%2];" \
        : "=r"((r)[0]), "=r"((r)[1]) : "r"(addr))

__device__ __forceinline__ void mma_bf16(float* d, const uint32_t* a, const uint32_t* b) {
    asm volatile("mma.sync.aligned.m16n8k16.row.col.f32.bf16.bf16.f32 "
                 "{%0,%1,%2,%3}, {%4,%5,%6,%7}, {%8,%9}, {%0,%1,%2,%3};"
                 : "+f"(d[0]), "+f"(d[1]), "+f"(d[2]), "+f"(d[3])
                 : "r"(a[0]), "r"(a[1]), "r"(a[2]), "r"(a[3]), "r"(b[0]), "r"(b[1]));
}

union BPack { __nv_bfloat162 h2[2]; uint2 u; };

// ---------------------------------------------------------------------------
// Kernel 1a: conv weights -> bf16 hi/lo, [r][tap][24 o (18 used, 6 zero)][1024 c]
// ---------------------------------------------------------------------------
__global__ void k_cwprep(const float* __restrict__ w1, const float* __restrict__ w2) {
    int idx = blockIdx.x * 256 + threadIdx.x;   // over 2*9*24*1024
    if (idx >= 2*9*24*1024) return;
    int c   = idx & 1023;
    int o   = (idx >> 10) % 24;
    int tap = (idx >> 10) / 24 % 9;
    int r   = idx / (24*1024*9);
    float v = 0.f;
    if (o < 18) {
        const float* w = r ? w2 : w1;
        v = w[o*9216 + c*9 + tap];
    }
    __nv_bfloat16 h = __float2bfloat16(v);
    g_cwhi[idx] = h;
    g_cwlo[idx] = __float2bfloat16(v - __bfloat162float(h));
}

// ---------------------------------------------------------------------------
// Kernel 1b: X -> bf16 hi/lo
// ---------------------------------------------------------------------------
__global__ void k_xprep(const float* __restrict__ x) {
    int idx = blockIdx.x * 256 + threadIdx.x;   // one per 4 floats, 2560*1024/4
    float4 v = *(const float4*)(x + (size_t)idx*4);
    BPack ph, pl;
    __nv_bfloat16 h;
    h = __float2bfloat16(v.x); ph.h2[0].x = h; pl.h2[0].x = __float2bfloat16(v.x - __bfloat162float(h));
    h = __float2bfloat16(v.y); ph.h2[0].y = h; pl.h2[0].y = __float2bfloat16(v.y - __bfloat162float(h));
    h = __float2bfloat16(v.z); ph.h2[1].x = h; pl.h2[1].x = __float2bfloat16(v.z - __bfloat162float(h));
    h = __float2bfloat16(v.w); ph.h2[1].y = h; pl.h2[1].y = __float2bfloat16(v.w - __bfloat162float(h));
    *(uint2*)(g_xhi + (size_t)idx*4) = ph.u;
    *(uint2*)(g_xlo + (size_t)idx*4) = pl.u;
}

// ---------------------------------------------------------------------------
// Kernel 1c: W_hidden -> bf16 hi/lo split
// ---------------------------------------------------------------------------
__global__ void k_wprep(const float* __restrict__ W) {
    int idx = blockIdx.x * 256 + threadIdx.x;     // one per 4 floats
    if (idx >= 1024*1024/4) return;
    float4 v = *(const float4*)(W + idx*4);
    BPack ph, pl;
    __nv_bfloat16 h;
    h = __float2bfloat16(v.x); ph.h2[0].x = h; pl.h2[0].x = __float2bfloat16(v.x - __bfloat162float(h));
    h = __float2bfloat16(v.y); ph.h2[0].y = h; pl.h2[0].y = __float2bfloat16(v.y - __bfloat162float(h));
    h = __float2bfloat16(v.z); ph.h2[1].x = h; pl.h2[1].x = __float2bfloat16(v.z - __bfloat162float(h));
    h = __float2bfloat16(v.w); ph.h2[1].y = h; pl.h2[1].y = __float2bfloat16(v.w - __bfloat162float(h));
    *(uint2*)(g_bhi + idx*4) = ph.u;
    *(uint2*)(g_blo + idx*4) = pl.u;
}

// ---------------------------------------------------------------------------
// Kernel 2: offset conv via HMMA (bf16 hi/lo 3-term split).
// grid = (40 pos-tiles of 64) x (8 channel-eighths of 128ch), block 256.
// 8 warps = 2 ratios x 4 m16-tiles (16 positions each, fixed t row).
// Per K-chunk (16 ch): zero-padded X halo tile [160 rows][16ch] hi+lo in smem,
// W [r][tap][mat][24 o rows][16ch]. ldmatrix gathers shifted rows per tap.
// D[m=pos 16][n=o 24] fp32 accum in regs (3 n8 tiles).
// ---------------------------------------------------------------------------
#define XMAT  5120                    // 160 rows * 32B per matrix
#define XBUF  (2*XMAT)                // hi + lo = 10240
#define WBUF  27648                   // 2r*9tap*2mat*24rows*32B
#define CT_SMEM (2*XBUF + 2*WBUF)     // 75776

__global__ void __launch_bounds__(256) k_conv_tc() {
    extern __shared__ __align__(16) char smem[];
    const uint32_t sb  = smem_u32(smem);
    const uint32_t sX0 = sb;
    const uint32_t sX1 = sb + XBUF;
    const uint32_t sW0 = sb + 2*XBUF;
    const uint32_t sW1 = sW0 + WBUF;

    const int tile = blockIdx.x;      // 0..39 = b*5 + tq
    const int e    = blockIdx.y;      // 0..7 channel-eighth (128 ch)
    const int b    = tile / 5;
    const int t0   = (tile - b*5) * 4;
    const int chb  = e * 128;

    const int tid  = threadIdx.x;
    const int wid  = tid >> 5, lane = tid & 31;
    const int rr   = wid >> 2;        // ratio index
    const int mt   = wid & 3;         // m16 tile = t row (t0+mt)
    const int ratio = rr + 1;

    // zero X buffers (invalid halo rows stay zero forever)
    for (int i = tid; i < 2*XBUF/4; i += 256)
        ((uint32_t*)smem)[i] = 0;

    // ---- X loader slots (3): 640 16B ops/chunk ----
    const __nv_bfloat16* xsrc[3];
    uint32_t xdst[3];
    #pragma unroll
    for (int k = 0; k < 3; k++) {
        int idx = tid + k*256;
        xsrc[k] = nullptr;
        if (idx < 640) {
            int h   = idx & 1;
            int mat = (idx >> 1) & 1;
            int row = idx >> 2;              // 0..159
            int tt = t0 + row/20 - 2, nn = row%20 - 2;
            xdst[k] = (uint32_t)(mat*XMAT + row*32 + h*16);
            if (tt >= 0 && tt < TT && nn >= 0 && nn < TN)
                xsrc[k] = (mat ? g_xlo : g_xhi)
                        + (size_t)((b*TT + tt)*TN + nn)*1024 + h*8;
        }
    }
    // ---- W loader slots (7): 1728 16B ops/chunk; dst = idx*16 ----
    const __nv_bfloat16* wsrc[7];
    #pragma unroll
    for (int k = 0; k < 7; k++) {
        int idx = tid + k*256;
        wsrc[k] = nullptr;
        if (idx < 1728) {
            int h    = idx & 1;
            int row  = (idx >> 1) % 24;
            int mat  = (idx >> 1) / 24 % 2;
            int rtap = idx / 96;             // r*9+tap
            wsrc[k] = (mat ? g_cwlo : g_cwhi)
                    + (size_t)(rtap*24 + row)*1024 + h*8;
        }
    }
    __syncthreads();

#define CT_ISSUE(ck, bX, bW) do { \
        int _c = chb + (ck)*16; \
        _Pragma("unroll") \
        for (int k = 0; k < 3; k++) \
            if (xsrc[k]) cp_async16((bX) + xdst[k], xsrc[k] + _c); \
        _Pragma("unroll") \
        for (int k = 0; k < 7; k++) \
            if (wsrc[k]) cp_async16((bW) + (uint32_t)(tid + k*256)*16, wsrc[k] + _c); \
        CP_COMMIT(); \
    } while (0)

    CT_ISSUE(0, sX0, sW0);

    float acc[3][4];
    #pragma unroll
    for (int nt = 0; nt < 3; nt++)
        #pragma unroll
        for (int q = 0; q < 4; q++) acc[nt][q] = 0.f;

    const uint32_t laneA = (uint32_t)((lane & 15)*32 + (lane >> 4)*16);
    const uint32_t laneB = (uint32_t)((lane & 7)*32 + ((lane >> 3) & 1)*16);

    for (int ck = 0; ck < 8; ck++) {
        const uint32_t bX = (ck & 1) ? sX1 : sX0;
        const uint32_t bW = (ck & 1) ? sW1 : sW0;
        CP_WAIT0();
        __syncthreads();
        if (ck < 7) CT_ISSUE(ck + 1, (ck & 1) ? sX0 : sX1, (ck & 1) ? sW0 : sW1);

        #pragma unroll
        for (int tap = 0; tap < 9; tap++) {
            const int dt = tap/3 - 1, dn = tap%3 - 1;
            const int tp = mt + dt*ratio + 2;              // 0..7
            const uint32_t abase = bX + (uint32_t)((tp*20 + dn*ratio + 2)*32);
            uint32_t ah[4], al[4];
            LDM4(ah, abase + laneA);
            LDM4(al, abase + XMAT + laneA);
            const uint32_t wbase = bW + (uint32_t)((rr*9 + tap)*1536);
            #pragma unroll
            for (int nt = 0; nt < 3; nt++) {
                uint32_t bh[2], bl[2];
                LDM2(bh, wbase + (uint32_t)(nt*256) + laneB);
                LDM2(bl, wbase + 768u + (uint32_t)(nt*256) + laneB);
                mma_bf16(acc[nt], ah, bh);
                mma_bf16(acc[nt], ah, bl);
                mma_bf16(acc[nt], al, bh);
            }
        }
    }
#undef CT_ISSUE

    // epilogue: D rows = n-positions, cols = outputs (18 of 24 valid)
    const int r0 = lane >> 2;
    const int c0 = (lane & 3) * 2;
    const int posbase = b*320 + (t0 + mt)*16;
    #pragma unroll
    for (int nt = 0; nt < 3; nt++) {
        int o = nt*8 + c0;
        if (o < 18) {
            float* d0 = g_offp + ((size_t)(e*2 + rr)*NPOS + posbase + r0)*18 + o;
            float* d1 = g_offp + ((size_t)(e*2 + rr)*NPOS + posbase + r0 + 8)*18 + o;
            *(float2*)d0 = make_float2(acc[nt][0], acc[nt][1]);
            *(float2*)d1 = make_float2(acc[nt][2], acc[nt][3]);
        }
    }
}

// ---------------------------------------------------------------------------
// Kernel 3: deformable bilinear gather (R12 form; 16 partial slices).
// ---------------------------------------------------------------------------
__global__ void __launch_bounds__(256) k_gather(const float* __restrict__ x,
                                                const float* __restrict__ b1,
                                                const float* __restrict__ b2,
                                                float* __restrict__ out_ftmad,
                                                int write_ftmad) {
    int pos = blockIdx.x;
    int bb  = pos / 320; int rem = pos - bb*320;
    int t   = rem >> 4,  n = rem & 15;

    __shared__ int   s_off[2][9][4];
    __shared__ float s_coe[2][9][4];

    int tid = threadIdx.x;
    if (tid < 18) {
        int r = tid / 9, k = tid - r*9;
        int ratio = r + 1;
        const float* bias = r ? b2 : b1;
        float offt = bias[k], offn = bias[k + 9];
        #pragma unroll
        for (int q = 0; q < 8; q++) {
            const float* op = g_offp + ((size_t)(q*2 + r)*NPOS + pos)*18;
            offt += op[k];
            offn += op[k + 9];
        }
        float Tp1 = (float)(TT + 2*ratio - 1);
        float Np1 = (float)(TN + 2*ratio - 1);
        float post = (float)(t + ratio) + (float)((k/3 - 1)*ratio) + offt;
        float posn = (float)(n + ratio) + (float)((k%3 - 1)*ratio) + offn;
        float flt = floorf(post), fln = floorf(posn);
        float ltt = fminf(fmaxf(flt,       0.f), Tp1);
        float ltn = fminf(fmaxf(fln,       0.f), Np1);
        float rbt = fminf(fmaxf(flt + 1.f, 0.f), Tp1);
        float rbn = fminf(fmaxf(fln + 1.f, 0.f), Np1);
        float pct = fminf(fmaxf(post, 0.f), Tp1);
        float pcn = fminf(fmaxf(posn, 0.f), Np1);
        float wltt = 1.f - fabsf(pct - ltt);
        float wrbt = 1.f - fabsf(pct - rbt);
        float wltn = 1.f - fabsf(pcn - ltn);
        float wrbn = 1.f - fabsf(pcn - rbn);
        s_coe[r][k][0] = wltt * wltn;
        s_coe[r][k][1] = wrbt * wrbn;
        s_coe[r][k][2] = wrbt * wltn;
        s_coe[r][k][3] = wltt * wrbn;
        int ict[4] = {(int)ltt, (int)rbt, (int)rbt, (int)ltt};
        int icn[4] = {(int)ltn, (int)rbn, (int)ltn, (int)rbn};
        #pragma unroll
        for (int q = 0; q < 4; q++) {
            int ts = ict[q] - ratio, ns = icn[q] - ratio;
            s_off[r][k][q] = ((unsigned)ts < (unsigned)TT && (unsigned)ns < (unsigned)TN)
                           ? ((bb*TT + ts)*TN + ns)*TC : -1;
        }
    }
    __syncthreads();

    int c = tid * 4;
    float dx = 0.f, dy = 0.f, dz = 0.f, dw = 0.f;
    #pragma unroll
    for (int r = 0; r < 2; r++) {
        #pragma unroll
        for (int k = 0; k < 9; k++) {
            float fx = 0.f, fy = 0.f, fz = 0.f, fw = 0.f;
            #pragma unroll
            for (int q = 0; q < 4; q++) {
                int   o   = s_off[r][k][q];
                float coe = s_coe[r][k][q];
                if (o >= 0) {
                    float4 v = *(const float4*)(x + o + c);
                    fx = fmaf(coe, v.x, fx);
                    fy = fmaf(coe, v.y, fy);
                    fz = fmaf(coe, v.z, fz);
                    fw = fmaf(coe, v.w, fw);
                }
            }
            if (r == 1 && write_ftmad) {
                float4 ov = make_float4(fx, fy, fz, fw);
                *(float4*)(out_ftmad + (pos*9 + k)*1024 + c) = ov;
            }
            dx += fx; dy += fy; dz += fz; dw += fw;
        }
    }
    const float s = 1.f / 18.f;
    float4 dv = make_float4(dx*s, dy*s, dz*s, dw*s);

    BPack ph, pl;
    __nv_bfloat16 h;
    h = __float2bfloat16(dv.x); ph.h2[0].x = h; pl.h2[0].x = __float2bfloat16(dv.x - __bfloat162float(h));
    h = __float2bfloat16(dv.y); ph.h2[0].y = h; pl.h2[0].y = __float2bfloat16(dv.y - __bfloat162float(h));
    h = __float2bfloat16(dv.z); ph.h2[1].x = h; pl.h2[1].x = __float2bfloat16(dv.z - __bfloat162float(h));
    h = __float2bfloat16(dv.w); ph.h2[1].y = h; pl.h2[1].y = __float2bfloat16(dv.w - __bfloat162float(h));
    *(uint2*)(g_ahi + (long)pos*1024 + c) = ph.u;
    *(uint2*)(g_alo + (long)pos*1024 + c) = pl.u;
}

// ---------------------------------------------------------------------------
// Kernel 4: HMMA split GEMM v1c (R12 — known-good): M128xN64, 320 CTAs,
// occ 2, cp.async double-buffered, 1 sync per slab.
// ---------------------------------------------------------------------------
#define KC       32
#define NSLAB    (1024/KC)
#define SA       80
#define S_AHI    0
#define S_ALO    (128*SA)
#define S_BHI    (2*128*SA)
#define S_BLO    (2*128*SA + 64*SA)
#define STG      (2*128*SA + 2*64*SA)
#define GSMEM    (2*STG)

__global__ void __launch_bounds__(256, 2) k_gemm_mma(float* __restrict__ out) {
    extern __shared__ __align__(16) char smem[];
    const uint32_t sb = smem_u32(smem);

    const int tid  = threadIdx.x;
    const int wid  = tid >> 5;
    const int lane = tid & 31;
    const int bx   = blockIdx.x;      // N tile of 64 (0..15)
    const int by   = blockIdx.y;      // M tile of 128 (0..19)
    const int wy   = wid & 3;
    const int wx   = wid >> 2;

    const __nv_bfloat16* pAhi = g_ahi + (size_t)by*128*1024;
    const __nv_bfloat16* pAlo = g_alo + (size_t)by*128*1024;
    const __nv_bfloat16* pBhi = g_bhi + (size_t)bx*64*1024;
    const __nv_bfloat16* pBlo = g_blo + (size_t)bx*64*1024;

    const int lrow = tid >> 2, lc4 = tid & 3;
    const size_t ga0 = (size_t)lrow*1024 + lc4*8;
    const size_t ga1 = (size_t)(lrow+64)*1024 + lc4*8;
    const uint32_t sa0 = (uint32_t)(lrow*SA + lc4*16);
    const uint32_t sa1 = (uint32_t)((lrow+64)*SA + lc4*16);

    float acc[2][4][4];
    #pragma unroll
    for (int i = 0; i < 2; i++)
        #pragma unroll
        for (int j = 0; j < 4; j++)
            #pragma unroll
            for (int q = 0; q < 4; q++) acc[i][j][q] = 0.f;

    const uint32_t laneA = (uint32_t)((lane & 15)*SA + (lane >> 4)*16);
    const uint32_t laneB = (uint32_t)((lane & 7)*SA + ((lane >> 3) & 1)*16);

#define GEMM_ISSUE(k0, bufbase) do { \
        cp_async16((bufbase) + S_AHI + sa0, pAhi + ga0 + (k0)); \
        cp_async16((bufbase) + S_AHI + sa1, pAhi + ga1 + (k0)); \
        cp_async16((bufbase) + S_ALO + sa0, pAlo + ga0 + (k0)); \
        cp_async16((bufbase) + S_ALO + sa1, pAlo + ga1 + (k0)); \
        cp_async16((bufbase) + S_BHI + sa0, pBhi + ga0 + (k0)); \
        cp_async16((bufbase) + S_BLO + sa0, pBlo + ga0 + (k0)); \
        CP_COMMIT(); \
    } while (0)

    GEMM_ISSUE(0, sb);

    for (int s = 0; s < NSLAB; s++) {
        const uint32_t base = sb + (uint32_t)(s & 1)*STG;
        CP_WAIT0();
        __syncthreads();
        if (s + 1 < NSLAB)
            GEMM_ISSUE((size_t)(s + 1)*KC, sb + (uint32_t)((s + 1) & 1)*STG);

        #pragma unroll
        for (int kk = 0; kk < 2; kk++) {
            uint32_t kB = kk * 32;
            uint32_t ah[2][4], al[2][4], bh[4][2], bl[4][2];
            #pragma unroll
            for (int mi = 0; mi < 2; mi++) {
                uint32_t moff = (uint32_t)((wy*32 + mi*16)*SA) + kB + laneA;
                LDM4(ah[mi], base + S_AHI + moff);
                LDM4(al[mi], base + S_ALO + moff);
            }
            #pragma unroll
            for (int ni = 0; ni < 4; ni++) {
                uint32_t noff = (uint32_t)((wx*32 + ni*8)*SA) + kB + laneB;
                LDM2(bh[ni], base + S_BHI + noff);
                LDM2(bl[ni], base + S_BLO + noff);
            }
            #pragma unroll
            for (int mi = 0; mi < 2; mi++)
                #pragma unroll
                for (int ni = 0; ni < 4; ni++) {
                    mma_bf16(acc[mi][ni], ah[mi], bh[ni]);
                    mma_bf16(acc[mi][ni], ah[mi], bl[ni]);
                    mma_bf16(acc[mi][ni], al[mi], bh[ni]);
                }
        }
    }
#undef GEMM_ISSUE

    const int r0 = (lane >> 2);
    const int c0 = (lane & 3) * 2;
    #pragma unroll
    for (int mi = 0; mi < 2; mi++) {
        #pragma unroll
        for (int ni = 0; ni < 4; ni++) {
            size_t row = (size_t)by*128 + wy*32 + mi*16 + r0;
            size_t col = (size_t)bx*64 + wx*32 + ni*8 + c0;
            *(float2*)(out + row*1024 + col)       = make_float2(acc[mi][ni][0], acc[mi][ni][1]);
            *(float2*)(out + (row + 8)*1024 + col) = make_float2(acc[mi][ni][2], acc[mi][ni][3]);
        }
    }
}

// ---------------------------------------------------------------------------
extern "C" void kernel_launch(void* const* d_in, const int* in_sizes, int n_in,
                              void* d_out, int out_size) {
    const float* xf  = (const float*)d_in[0];  // person_features [8,20,16,1024]
    const float* Wh  = (const float*)d_in[1];  // W_hidden [1024,1024]
    const float* w1  = (const float*)d_in[2];  // p_w1 [18,1024,3,3]
    const float* bb1 = (const float*)d_in[3];  // p_b1 [18]
    const float* w2  = (const float*)d_in[4];  // p_w2 [18,1024,3,3]
    const float* bb2 = (const float*)d_in[5];  // p_b2 [18]
    (void)in_sizes; (void)n_in;

    float* out       = (float*)d_out;
    float* out_dyn   = out;                       // [2560,1024]
    float* out_ftmad = out + (long)NPOS * TC;     // [2560,9,1024]
    int write_ftmad  = (out_size >= NPOS*TC + NPOS*9*TC) ? 1 : 0;

    cudaFuncSetAttribute(k_gemm_mma, cudaFuncAttributeMaxDynamicSharedMemorySize,
                         GSMEM);
    cudaFuncSetAttribute(k_conv_tc, cudaFuncAttributeMaxDynamicSharedMemorySize,
                         CT_SMEM);

    k_cwprep<<<(2*9*24*1024 + 255)/256, 256>>>(w1, w2);
    k_xprep<<<NPOS, 256>>>(xf);
    k_wprep<<<1024, 256>>>(Wh);

    dim3 gconv(40, 8);
    k_conv_tc<<<gconv, 256, CT_SMEM>>>();

    k_gather<<<NPOS, 256>>>(xf, bb1, bb2, out_ftmad, write_ftmad);

    dim3 ggemm(16, 20);
    k_gemm_mma<<<ggemm, 256, GSMEM>>>(out_dyn);
}

// round 16
// speedup vs baseline: 1.1215x; 1.0003x over previous
#include <cuda_runtime.h>
#include <cuda_bf16.h>
#include <cstdint>

typedef unsigned long long ull;

// Problem constants
#define TB   8
#define TT   20
#define TN   16
#define TC   1024
#define NPOS 2560          // B*T*N
#define NO   18            // 2*K2

// Scratch (allocation-free rule: __device__ globals)
__device__ float g_offp[16*NPOS*18];           // conv partials: 8 eighths x 2 ratios
__device__ __nv_bfloat16 g_xhi[NPOS*TC];       // X hi (for tensor conv)
__device__ __nv_bfloat16 g_xlo[NPOS*TC];       // X lo
__device__ __nv_bfloat16 g_cwhi[2*9*24*1024];  // conv W hi [r][tap][24 o(pad)][c]
__device__ __nv_bfloat16 g_cwlo[2*9*24*1024];  // conv W lo
__device__ __nv_bfloat16 g_ahi[NPOS*TC];       // A hi (from gather)
__device__ __nv_bfloat16 g_alo[NPOS*TC];       // A lo
__device__ __nv_bfloat16 g_bhi[1024*1024];     // W_hidden hi
__device__ __nv_bfloat16 g_blo[1024*1024];     // W_hidden lo

__device__ __forceinline__ uint32_t smem_u32(const void* p) {
    uint32_t a;
    asm("{ .reg .u64 t; cvta.to.shared.u64 t, %1; cvt.u32.u64 %0, t; }"
        : "=r"(a) : "l"(p));
    return a;
}
__device__ __forceinline__ void cp_async16(uint32_t dst, const void* src) {
    asm volatile("cp.async.ca.shared.global [%0], [%1], 16;" :: "r"(dst), "l"(src));
}
#define CP_COMMIT() asm volatile("cp.async.commit_group;" ::: "memory")
#define CP_WAIT0()  asm volatile("cp.async.wait_group 0;" ::: "memory")

#define LDM4(r, addr) \
    asm volatile("ldmatrix.sync.aligned.m8n8.x4.shared.b16 {%0,%1,%2,%3}, [%4];" \
        : "=r"((r)[0]), "=r"((r)[1]), "=r"((r)[2]), "=r"((r)[3]) : "r"(addr))
#define LDM2(r, addr) \
    asm volatile("ldmatrix.sync.aligned.m8n8.x2.shared.b16 {%0,%1}, [%2];" \
        : "=r"((r)[0]), "=r"((r)[1]) : "r"(addr))

__device__ __forceinline__ void mma_bf16(float* d, const uint32_t* a, const uint32_t* b) {
    asm volatile("mma.sync.aligned.m16n8k16.row.col.f32.bf16.bf16.f32 "
                 "{%0,%1,%2,%3}, {%4,%5,%6,%7}, {%8,%9}, {%0,%1,%2,%3};"
                 : "+f"(d[0]), "+f"(d[1]), "+f"(d[2]), "+f"(d[3])
                 : "r"(a[0]), "r"(a[1]), "r"(a[2]), "r"(a[3]), "r"(b[0]), "r"(b[1]));
}

union BPack { __nv_bfloat162 h2[2]; uint2 u; };

// ---------------------------------------------------------------------------
// Kernel 1a: conv weights -> bf16 hi/lo, [r][tap][24 o (18 used, 6 zero)][1024 c]
// ---------------------------------------------------------------------------
__global__ void k_cwprep(const float* __restrict__ w1, const float* __restrict__ w2) {
    int idx = blockIdx.x * 256 + threadIdx.x;   // over 2*9*24*1024
    if (idx >= 2*9*24*1024) return;
    int c   = idx & 1023;
    int o   = (idx >> 10) % 24;
    int tap = (idx >> 10) / 24 % 9;
    int r   = idx / (24*1024*9);
    float v = 0.f;
    if (o < 18) {
        const float* w = r ? w2 : w1;
        v = w[o*9216 + c*9 + tap];
    }
    __nv_bfloat16 h = __float2bfloat16(v);
    g_cwhi[idx] = h;
    g_cwlo[idx] = __float2bfloat16(v - __bfloat162float(h));
}

// ---------------------------------------------------------------------------
// Kernel 1b: X -> bf16 hi/lo
// ---------------------------------------------------------------------------
__global__ void k_xprep(const float* __restrict__ x) {
    int idx = blockIdx.x * 256 + threadIdx.x;   // one per 4 floats, 2560*1024/4
    float4 v = *(const float4*)(x + (size_t)idx*4);
    BPack ph, pl;
    __nv_bfloat16 h;
    h = __float2bfloat16(v.x); ph.h2[0].x = h; pl.h2[0].x = __float2bfloat16(v.x - __bfloat162float(h));
    h = __float2bfloat16(v.y); ph.h2[0].y = h; pl.h2[0].y = __float2bfloat16(v.y - __bfloat162float(h));
    h = __float2bfloat16(v.z); ph.h2[1].x = h; pl.h2[1].x = __float2bfloat16(v.z - __bfloat162float(h));
    h = __float2bfloat16(v.w); ph.h2[1].y = h; pl.h2[1].y = __float2bfloat16(v.w - __bfloat162float(h));
    *(uint2*)(g_xhi + (size_t)idx*4) = ph.u;
    *(uint2*)(g_xlo + (size_t)idx*4) = pl.u;
}

// ---------------------------------------------------------------------------
// Kernel 1c: W_hidden -> bf16 hi/lo split
// ---------------------------------------------------------------------------
__global__ void k_wprep(const float* __restrict__ W) {
    int idx = blockIdx.x * 256 + threadIdx.x;     // one per 4 floats
    if (idx >= 1024*1024/4) return;
    float4 v = *(const float4*)(W + idx*4);
    BPack ph, pl;
    __nv_bfloat16 h;
    h = __float2bfloat16(v.x); ph.h2[0].x = h; pl.h2[0].x = __float2bfloat16(v.x - __bfloat162float(h));
    h = __float2bfloat16(v.y); ph.h2[0].y = h; pl.h2[0].y = __float2bfloat16(v.y - __bfloat162float(h));
    h = __float2bfloat16(v.z); ph.h2[1].x = h; pl.h2[1].x = __float2bfloat16(v.z - __bfloat162float(h));
    h = __float2bfloat16(v.w); ph.h2[1].y = h; pl.h2[1].y = __float2bfloat16(v.w - __bfloat162float(h));
    *(uint2*)(g_bhi + idx*4) = ph.u;
    *(uint2*)(g_blo + idx*4) = pl.u;
}

// ---------------------------------------------------------------------------
// Kernel 2: offset conv via HMMA v2 — per-ratio CTAs for latency hiding.
// grid = (40 pos-tiles of 64) x (16 = 8 channel-eighths x 2 ratios),
// block 128 = 4 warps = 4 m16-tiles. smem 48128 B -> 4 CTAs/SM.
// Per K-chunk (16 ch): X halo tile [160 rows][16ch] hi+lo, W (this ratio's
// 9 taps) [tap][mat][24 o][16ch]. Term-major mma: same-acc reuse distance 3.
// ---------------------------------------------------------------------------
#define XMAT   5120                   // 160 rows * 32B per matrix
#define XBUF   (2*XMAT)               // hi + lo = 10240
#define WBUFR  13824                  // 9tap*2mat*24rows*32B
#define CT_SMEM (2*XBUF + 2*WBUFR)    // 48128

__global__ void __launch_bounds__(128) k_conv_tc() {
    extern __shared__ __align__(16) char smem[];
    const uint32_t sb  = smem_u32(smem);
    const uint32_t sX0 = sb;
    const uint32_t sX1 = sb + XBUF;
    const uint32_t sW0 = sb + 2*XBUF;
    const uint32_t sW1 = sW0 + WBUFR;

    const int tile = blockIdx.x;      // 0..39 = b*5 + tq
    const int e    = blockIdx.y & 7;  // channel-eighth (128 ch)
    const int rr   = blockIdx.y >> 3; // ratio index
    const int b    = tile / 5;
    const int t0   = (tile - b*5) * 4;
    const int chb  = e * 128;
    const int ratio = rr + 1;

    const int tid  = threadIdx.x;
    const int wid  = tid >> 5, lane = tid & 31;
    const int mt   = wid;             // m16 tile = t row (t0+mt)

    // zero X buffers (invalid halo rows stay zero forever)
    for (int i = tid; i < 2*XBUF/4; i += 128)
        ((uint32_t*)smem)[i] = 0;

    // ---- X loader slots (5): 640 16B ops/chunk ----
    const __nv_bfloat16* xsrc[5];
    uint32_t xdst[5];
    #pragma unroll
    for (int k = 0; k < 5; k++) {
        int idx = tid + k*128;
        int h   = idx & 1;
        int mat = (idx >> 1) & 1;
        int row = idx >> 2;              // 0..159
        int tt = t0 + row/20 - 2, nn = row%20 - 2;
        xdst[k] = (uint32_t)(mat*XMAT + row*32 + h*16);
        xsrc[k] = (tt >= 0 && tt < TT && nn >= 0 && nn < TN)
                ? (mat ? g_xlo : g_xhi) + (size_t)((b*TT + tt)*TN + nn)*1024 + h*8
                : nullptr;
    }
    // ---- W loader slots (7): 864 16B ops/chunk (this ratio only) ----
    const __nv_bfloat16* wsrc[7];
    #pragma unroll
    for (int k = 0; k < 7; k++) {
        int idx = tid + k*128;
        wsrc[k] = nullptr;
        if (idx < 864) {
            int h    = idx & 1;
            int row  = (idx >> 1) % 24;
            int mat  = (idx >> 1) / 24 % 2;
            int tap  = idx / 96;             // 0..8
            wsrc[k] = (mat ? g_cwlo : g_cwhi)
                    + (size_t)((rr*9 + tap)*24 + row)*1024 + h*8;
        }
    }
    __syncthreads();

#define CT_ISSUE(ck, bX, bW) do { \
        int _c = chb + (ck)*16; \
        _Pragma("unroll") \
        for (int k = 0; k < 5; k++) \
            if (xsrc[k]) cp_async16((bX) + xdst[k], xsrc[k] + _c); \
        _Pragma("unroll") \
        for (int k = 0; k < 7; k++) \
            if (wsrc[k]) cp_async16((bW) + (uint32_t)(tid + k*128)*16, wsrc[k] + _c); \
        CP_COMMIT(); \
    } while (0)

    CT_ISSUE(0, sX0, sW0);

    float acc[3][4];
    #pragma unroll
    for (int nt = 0; nt < 3; nt++)
        #pragma unroll
        for (int q = 0; q < 4; q++) acc[nt][q] = 0.f;

    const uint32_t laneA = (uint32_t)((lane & 15)*32 + (lane >> 4)*16);
    const uint32_t laneB = (uint32_t)((lane & 7)*32 + ((lane >> 3) & 1)*16);

    for (int ck = 0; ck < 8; ck++) {
        const uint32_t bX = (ck & 1) ? sX1 : sX0;
        const uint32_t bW = (ck & 1) ? sW1 : sW0;
        CP_WAIT0();
        __syncthreads();
        if (ck < 7) CT_ISSUE(ck + 1, (ck & 1) ? sX0 : sX1, (ck & 1) ? sW0 : sW1);

        #pragma unroll
        for (int tap = 0; tap < 9; tap++) {
            const int dt = tap/3 - 1, dn = tap%3 - 1;
            const int tp = mt + dt*ratio + 2;              // 0..7
            const uint32_t abase = bX + (uint32_t)((tp*20 + dn*ratio + 2)*32);
            uint32_t ah[4], al[4];
            LDM4(ah, abase + laneA);
            LDM4(al, abase + XMAT + laneA);
            const uint32_t wbase = bW + (uint32_t)(tap*1536);
            uint32_t bh[3][2], bl[3][2];
            #pragma unroll
            for (int nt = 0; nt < 3; nt++) {
                LDM2(bh[nt], wbase + (uint32_t)(nt*256) + laneB);
                LDM2(bl[nt], wbase + 768u + (uint32_t)(nt*256) + laneB);
            }
            // term-major: same-accumulator reuse distance = 3
            #pragma unroll
            for (int nt = 0; nt < 3; nt++) mma_bf16(acc[nt], ah, bh[nt]);
            #pragma unroll
            for (int nt = 0; nt < 3; nt++) mma_bf16(acc[nt], ah, bl[nt]);
            #pragma unroll
            for (int nt = 0; nt < 3; nt++) mma_bf16(acc[nt], al, bh[nt]);
        }
    }
#undef CT_ISSUE

    // epilogue: D rows = n-positions, cols = outputs (18 of 24 valid)
    const int r0 = lane >> 2;
    const int c0 = (lane & 3) * 2;
    const int posbase = b*320 + (t0 + mt)*16;
    #pragma unroll
    for (int nt = 0; nt < 3; nt++) {
        int o = nt*8 + c0;
        if (o < 18) {
            float* d0 = g_offp + ((size_t)(e*2 + rr)*NPOS + posbase + r0)*18 + o;
            float* d1 = g_offp + ((size_t)(e*2 + rr)*NPOS + posbase + r0 + 8)*18 + o;
            *(float2*)d0 = make_float2(acc[nt][0], acc[nt][1]);
            *(float2*)d1 = make_float2(acc[nt][2], acc[nt][3]);
        }
    }
}

// ---------------------------------------------------------------------------
// Kernel 3: deformable bilinear gather (R12 form; 16 partial slices).
// ---------------------------------------------------------------------------
__global__ void __launch_bounds__(256) k_gather(const float* __restrict__ x,
                                                const float* __restrict__ b1,
                                                const float* __restrict__ b2,
                                                float* __restrict__ out_ftmad,
                                                int write_ftmad) {
    int pos = blockIdx.x;
    int bb  = pos / 320; int rem = pos - bb*320;
    int t   = rem >> 4,  n = rem & 15;

    __shared__ int   s_off[2][9][4];
    __shared__ float s_coe[2][9][4];

    int tid = threadIdx.x;
    if (tid < 18) {
        int r = tid / 9, k = tid - r*9;
        int ratio = r + 1;
        const float* bias = r ? b2 : b1;
        float offt = bias[k], offn = bias[k + 9];
        #pragma unroll
        for (int q = 0; q < 8; q++) {
            const float* op = g_offp + ((size_t)(q*2 + r)*NPOS + pos)*18;
            offt += op[k];
            offn += op[k + 9];
        }
        float Tp1 = (float)(TT + 2*ratio - 1);
        float Np1 = (float)(TN + 2*ratio - 1);
        float post = (float)(t + ratio) + (float)((k/3 - 1)*ratio) + offt;
        float posn = (float)(n + ratio) + (float)((k%3 - 1)*ratio) + offn;
        float flt = floorf(post), fln = floorf(posn);
        float ltt = fminf(fmaxf(flt,       0.f), Tp1);
        float ltn = fminf(fmaxf(fln,       0.f), Np1);
        float rbt = fminf(fmaxf(flt + 1.f, 0.f), Tp1);
        float rbn = fminf(fmaxf(fln + 1.f, 0.f), Np1);
        float pct = fminf(fmaxf(post, 0.f), Tp1);
        float pcn = fminf(fmaxf(posn, 0.f), Np1);
        float wltt = 1.f - fabsf(pct - ltt);
        float wrbt = 1.f - fabsf(pct - rbt);
        float wltn = 1.f - fabsf(pcn - ltn);
        float wrbn = 1.f - fabsf(pcn - rbn);
        s_coe[r][k][0] = wltt * wltn;
        s_coe[r][k][1] = wrbt * wrbn;
        s_coe[r][k][2] = wrbt * wltn;
        s_coe[r][k][3] = wltt * wrbn;
        int ict[4] = {(int)ltt, (int)rbt, (int)rbt, (int)ltt};
        int icn[4] = {(int)ltn, (int)rbn, (int)ltn, (int)rbn};
        #pragma unroll
        for (int q = 0; q < 4; q++) {
            int ts = ict[q] - ratio, ns = icn[q] - ratio;
            s_off[r][k][q] = ((unsigned)ts < (unsigned)TT && (unsigned)ns < (unsigned)TN)
                           ? ((bb*TT + ts)*TN + ns)*TC : -1;
        }
    }
    __syncthreads();

    int c = tid * 4;
    float dx = 0.f, dy = 0.f, dz = 0.f, dw = 0.f;
    #pragma unroll
    for (int r = 0; r < 2; r++) {
        #pragma unroll
        for (int k = 0; k < 9; k++) {
            float fx = 0.f, fy = 0.f, fz = 0.f, fw = 0.f;
            #pragma unroll
            for (int q = 0; q < 4; q++) {
                int   o   = s_off[r][k][q];
                float coe = s_coe[r][k][q];
                if (o >= 0) {
                    float4 v = *(const float4*)(x + o + c);
                    fx = fmaf(coe, v.x, fx);
                    fy = fmaf(coe, v.y, fy);
                    fz = fmaf(coe, v.z, fz);
                    fw = fmaf(coe, v.w, fw);
                }
            }
            if (r == 1 && write_ftmad) {
                float4 ov = make_float4(fx, fy, fz, fw);
                *(float4*)(out_ftmad + (pos*9 + k)*1024 + c) = ov;
            }
            dx += fx; dy += fy; dz += fz; dw += fw;
        }
    }
    const float s = 1.f / 18.f;
    float4 dv = make_float4(dx*s, dy*s, dz*s, dw*s);

    BPack ph, pl;
    __nv_bfloat16 h;
    h = __float2bfloat16(dv.x); ph.h2[0].x = h; pl.h2[0].x = __float2bfloat16(dv.x - __bfloat162float(h));
    h = __float2bfloat16(dv.y); ph.h2[0].y = h; pl.h2[0].y = __float2bfloat16(dv.y - __bfloat162float(h));
    h = __float2bfloat16(dv.z); ph.h2[1].x = h; pl.h2[1].x = __float2bfloat16(dv.z - __bfloat162float(h));
    h = __float2bfloat16(dv.w); ph.h2[1].y = h; pl.h2[1].y = __float2bfloat16(dv.w - __bfloat162float(h));
    *(uint2*)(g_ahi + (long)pos*1024 + c) = ph.u;
    *(uint2*)(g_alo + (long)pos*1024 + c) = pl.u;
}

// ---------------------------------------------------------------------------
// Kernel 4: HMMA split GEMM v1c (R12 — known-good): M128xN64, 320 CTAs,
// occ 2, cp.async double-buffered, 1 sync per slab.
// ---------------------------------------------------------------------------
#define KC       32
#define NSLAB    (1024/KC)
#define SA       80
#define S_AHI    0
#define S_ALO    (128*SA)
#define S_BHI    (2*128*SA)
#define S_BLO    (2*128*SA + 64*SA)
#define STG      (2*128*SA + 2*64*SA)
#define GSMEM    (2*STG)

__global__ void __launch_bounds__(256, 2) k_gemm_mma(float* __restrict__ out) {
    extern __shared__ __align__(16) char smem[];
    const uint32_t sb = smem_u32(smem);

    const int tid  = threadIdx.x;
    const int wid  = tid >> 5;
    const int lane = tid & 31;
    const int bx   = blockIdx.x;      // N tile of 64 (0..15)
    const int by   = blockIdx.y;      // M tile of 128 (0..19)
    const int wy   = wid & 3;
    const int wx   = wid >> 2;

    const __nv_bfloat16* pAhi = g_ahi + (size_t)by*128*1024;
    const __nv_bfloat16* pAlo = g_alo + (size_t)by*128*1024;
    const __nv_bfloat16* pBhi = g_bhi + (size_t)bx*64*1024;
    const __nv_bfloat16* pBlo = g_blo + (size_t)bx*64*1024;

    const int lrow = tid >> 2, lc4 = tid & 3;
    const size_t ga0 = (size_t)lrow*1024 + lc4*8;
    const size_t ga1 = (size_t)(lrow+64)*1024 + lc4*8;
    const uint32_t sa0 = (uint32_t)(lrow*SA + lc4*16);
    const uint32_t sa1 = (uint32_t)((lrow+64)*SA + lc4*16);

    float acc[2][4][4];
    #pragma unroll
    for (int i = 0; i < 2; i++)
        #pragma unroll
        for (int j = 0; j < 4; j++)
            #pragma unroll
            for (int q = 0; q < 4; q++) acc[i][j][q] = 0.f;

    const uint32_t laneA = (uint32_t)((lane & 15)*SA + (lane >> 4)*16);
    const uint32_t laneB = (uint32_t)((lane & 7)*SA + ((lane >> 3) & 1)*16);

#define GEMM_ISSUE(k0, bufbase) do { \
        cp_async16((bufbase) + S_AHI + sa0, pAhi + ga0 + (k0)); \
        cp_async16((bufbase) + S_AHI + sa1, pAhi + ga1 + (k0)); \
        cp_async16((bufbase) + S_ALO + sa0, pAlo + ga0 + (k0)); \
        cp_async16((bufbase) + S_ALO + sa1, pAlo + ga1 + (k0)); \
        cp_async16((bufbase) + S_BHI + sa0, pBhi + ga0 + (k0)); \
        cp_async16((bufbase) + S_BLO + sa0, pBlo + ga0 + (k0)); \
        CP_COMMIT(); \
    } while (0)

    GEMM_ISSUE(0, sb);

    for (int s = 0; s < NSLAB; s++) {
        const uint32_t base = sb + (uint32_t)(s & 1)*STG;
        CP_WAIT0();
        __syncthreads();
        if (s + 1 < NSLAB)
            GEMM_ISSUE((size_t)(s + 1)*KC, sb + (uint32_t)((s + 1) & 1)*STG);

        #pragma unroll
        for (int kk = 0; kk < 2; kk++) {
            uint32_t kB = kk * 32;
            uint32_t ah[2][4], al[2][4], bh[4][2], bl[4][2];
            #pragma unroll
            for (int mi = 0; mi < 2; mi++) {
                uint32_t moff = (uint32_t)((wy*32 + mi*16)*SA) + kB + laneA;
                LDM4(ah[mi], base + S_AHI + moff);
                LDM4(al[mi], base + S_ALO + moff);
            }
            #pragma unroll
            for (int ni = 0; ni < 4; ni++) {
                uint32_t noff = (uint32_t)((wx*32 + ni*8)*SA) + kB + laneB;
                LDM2(bh[ni], base + S_BHI + noff);
                LDM2(bl[ni], base + S_BLO + noff);
            }
            #pragma unroll
            for (int mi = 0; mi < 2; mi++)
                #pragma unroll
                for (int ni = 0; ni < 4; ni++) {
                    mma_bf16(acc[mi][ni], ah[mi], bh[ni]);
                    mma_bf16(acc[mi][ni], ah[mi], bl[ni]);
                    mma_bf16(acc[mi][ni], al[mi], bh[ni]);
                }
        }
    }
#undef GEMM_ISSUE

    const int r0 = (lane >> 2);
    const int c0 = (lane & 3) * 2;
    #pragma unroll
    for (int mi = 0; mi < 2; mi++) {
        #pragma unroll
        for (int ni = 0; ni < 4; ni++) {
            size_t row = (size_t)by*128 + wy*32 + mi*16 + r0;
            size_t col = (size_t)bx*64 + wx*32 + ni*8 + c0;
            *(float2*)(out + row*1024 + col)       = make_float2(acc[mi][ni][0], acc[mi][ni][1]);
            *(float2*)(out + (row + 8)*1024 + col) = make_float2(acc[mi][ni][2], acc[mi][ni][3]);
        }
    }
}

// ---------------------------------------------------------------------------
extern "C" void kernel_launch(void* const* d_in, const int* in_sizes, int n_in,
                              void* d_out, int out_size) {
    const float* xf  = (const float*)d_in[0];  // person_features [8,20,16,1024]
    const float* Wh  = (const float*)d_in[1];  // W_hidden [1024,1024]
    const float* w1  = (const float*)d_in[2];  // p_w1 [18,1024,3,3]
    const float* bb1 = (const float*)d_in[3];  // p_b1 [18]
    const float* w2  = (const float*)d_in[4];  // p_w2 [18,1024,3,3]
    const float* bb2 = (const float*)d_in[5];  // p_b2 [18]
    (void)in_sizes; (void)n_in;

    float* out       = (float*)d_out;
    float* out_dyn   = out;                       // [2560,1024]
    float* out_ftmad = out + (long)NPOS * TC;     // [2560,9,1024]
    int write_ftmad  = (out_size >= NPOS*TC + NPOS*9*TC) ? 1 : 0;

    cudaFuncSetAttribute(k_gemm_mma, cudaFuncAttributeMaxDynamicSharedMemorySize,
                         GSMEM);
    cudaFuncSetAttribute(k_conv_tc, cudaFuncAttributeMaxDynamicSharedMemorySize,
                         CT_SMEM);

    k_cwprep<<<(2*9*24*1024 + 255)/256, 256>>>(w1, w2);
    k_xprep<<<NPOS, 256>>>(xf);
    k_wprep<<<1024, 256>>>(Wh);

    dim3 gconv(40, 16);
    k_conv_tc<<<gconv, 128, CT_SMEM>>>();

    k_gather<<<NPOS, 256>>>(xf, bb1, bb2, out_ftmad, write_ftmad);

    dim3 ggemm(16, 20);
    k_gemm_mma<<<ggemm, 256, GSMEM>>>(out_dyn);
}

// round 17
// speedup vs baseline: 1.1952x; 1.0657x over previous
#include <cuda_runtime.h>
#include <cuda_bf16.h>
#include <cstdint>

typedef unsigned long long ull;

// Problem constants
#define TB   8
#define TT   20
#define TN   16
#define TC   1024
#define NPOS 2560          // B*T*N
#define NO   18            // 2*K2

// Scratch (allocation-free rule: __device__ globals)
__device__ float g_offp[16*NPOS*18];           // conv partials: 8 eighths x 2 ratios
__device__ __nv_bfloat16 g_xhi[NPOS*TC];       // X hi (for tensor conv)
__device__ __nv_bfloat16 g_xlo[NPOS*TC];       // X lo
__device__ __nv_bfloat16 g_cwhi[2*9*24*1024];  // conv W hi [r][tap][24 o(pad)][c]
__device__ __nv_bfloat16 g_cwlo[2*9*24*1024];  // conv W lo
__device__ __nv_bfloat16 g_ahi[NPOS*TC];       // A hi (from gather)
__device__ __nv_bfloat16 g_alo[NPOS*TC];       // A lo
__device__ __nv_bfloat16 g_bhi[1024*1024];     // W_hidden hi
__device__ __nv_bfloat16 g_blo[1024*1024];     // W_hidden lo

__device__ __forceinline__ uint32_t smem_u32(const void* p) {
    uint32_t a;
    asm("{ .reg .u64 t; cvta.to.shared.u64 t, %1; cvt.u32.u64 %0, t; }"
        : "=r"(a) : "l"(p));
    return a;
}
__device__ __forceinline__ void cp_async16(uint32_t dst, const void* src) {
    asm volatile("cp.async.ca.shared.global [%0], [%1], 16;" :: "r"(dst), "l"(src));
}
#define CP_COMMIT() asm volatile("cp.async.commit_group;" ::: "memory")
#define CP_WAIT0()  asm volatile("cp.async.wait_group 0;" ::: "memory")

#define LDM4(r, addr) \
    asm volatile("ldmatrix.sync.aligned.m8n8.x4.shared.b16 {%0,%1,%2,%3}, [%4];" \
        : "=r"((r)[0]), "=r"((r)[1]), "=r"((r)[2]), "=r"((r)[3]) : "r"(addr))
#define LDM2(r, addr) \
    asm volatile("ldmatrix.sync.aligned.m8n8.x2.shared.b16 {%0,%1}, [%2];" \
        : "=r"((r)[0]), "=r"((r)[1]) : "r"(addr))

__device__ __forceinline__ void mma_bf16(float* d, const uint32_t* a, const uint32_t* b) {
    asm volatile("mma.sync.aligned.m16n8k16.row.col.f32.bf16.bf16.f32 "
                 "{%0,%1,%2,%3}, {%4,%5,%6,%7}, {%8,%9}, {%0,%1,%2,%3};"
                 : "+f"(d[0]), "+f"(d[1]), "+f"(d[2]), "+f"(d[3])
                 : "r"(a[0]), "r"(a[1]), "r"(a[2]), "r"(a[3]), "r"(b[0]), "r"(b[1]));
}

union BPack { __nv_bfloat162 h2[2]; uint2 u; };

// ---------------------------------------------------------------------------
// Kernel 1a: conv weights -> bf16 hi/lo, [r][tap][24 o (18 used, 6 zero)][1024 c]
// ---------------------------------------------------------------------------
__global__ void k_cwprep(const float* __restrict__ w1, const float* __restrict__ w2) {
    int idx = blockIdx.x * 256 + threadIdx.x;   // over 2*9*24*1024
    if (idx >= 2*9*24*1024) return;
    int c   = idx & 1023;
    int o   = (idx >> 10) % 24;
    int tap = (idx >> 10) / 24 % 9;
    int r   = idx / (24*1024*9);
    float v = 0.f;
    if (o < 18) {
        const float* w = r ? w2 : w1;
        v = w[o*9216 + c*9 + tap];
    }
    __nv_bfloat16 h = __float2bfloat16(v);
    g_cwhi[idx] = h;
    g_cwlo[idx] = __float2bfloat16(v - __bfloat162float(h));
}

// ---------------------------------------------------------------------------
// Kernel 1b: X -> bf16 hi/lo
// ---------------------------------------------------------------------------
__global__ void k_xprep(const float* __restrict__ x) {
    int idx = blockIdx.x * 256 + threadIdx.x;   // one per 4 floats, 2560*1024/4
    float4 v = *(const float4*)(x + (size_t)idx*4);
    BPack ph, pl;
    __nv_bfloat16 h;
    h = __float2bfloat16(v.x); ph.h2[0].x = h; pl.h2[0].x = __float2bfloat16(v.x - __bfloat162float(h));
    h = __float2bfloat16(v.y); ph.h2[0].y = h; pl.h2[0].y = __float2bfloat16(v.y - __bfloat162float(h));
    h = __float2bfloat16(v.z); ph.h2[1].x = h; pl.h2[1].x = __float2bfloat16(v.z - __bfloat162float(h));
    h = __float2bfloat16(v.w); ph.h2[1].y = h; pl.h2[1].y = __float2bfloat16(v.w - __bfloat162float(h));
    *(uint2*)(g_xhi + (size_t)idx*4) = ph.u;
    *(uint2*)(g_xlo + (size_t)idx*4) = pl.u;
}

// ---------------------------------------------------------------------------
// Kernel 1c: W_hidden -> bf16 hi/lo split
// ---------------------------------------------------------------------------
__global__ void k_wprep(const float* __restrict__ W) {
    int idx = blockIdx.x * 256 + threadIdx.x;     // one per 4 floats
    if (idx >= 1024*1024/4) return;
    float4 v = *(const float4*)(W + idx*4);
    BPack ph, pl;
    __nv_bfloat16 h;
    h = __float2bfloat16(v.x); ph.h2[0].x = h; pl.h2[0].x = __float2bfloat16(v.x - __bfloat162float(h));
    h = __float2bfloat16(v.y); ph.h2[0].y = h; pl.h2[0].y = __float2bfloat16(v.y - __bfloat162float(h));
    h = __float2bfloat16(v.z); ph.h2[1].x = h; pl.h2[1].x = __float2bfloat16(v.z - __bfloat162float(h));
    h = __float2bfloat16(v.w); ph.h2[1].y = h; pl.h2[1].y = __float2bfloat16(v.w - __bfloat162float(h));
    *(uint2*)(g_bhi + idx*4) = ph.u;
    *(uint2*)(g_blo + idx*4) = pl.u;
}

// ---------------------------------------------------------------------------
// Kernel 2: offset conv via HMMA v3 — 18-row W buffers + zero-row trick.
// grid = (40 pos-tiles of 64) x (16 = 8 channel-eighths x 2 ratios),
// block 128 = 4 warps = 4 m16-tiles. smem 41248 B -> 5 CTAs/SM (single wave).
// W smem stores only the 18 real output rows; ldmatrix lanes for rows >= 18
// point at a shared 32B zero block (per-lane addressing makes this free).
// ---------------------------------------------------------------------------
#define XMAT   5120                   // 160 rows * 32B per matrix
#define XBUF   (2*XMAT)               // hi + lo = 10240
#define WBUFR  10368                  // 9tap*2mat*18rows*32B
#define ZOFF   (2*XBUF + 2*WBUFR)     // 41216: 32B zero block
#define CT_SMEM (ZOFF + 32)           // 41248

__global__ void __launch_bounds__(128, 5) k_conv_tc() {
    extern __shared__ __align__(16) char smem[];
    const uint32_t sb  = smem_u32(smem);
    const uint32_t sX0 = sb;
    const uint32_t sX1 = sb + XBUF;
    const uint32_t sW0 = sb + 2*XBUF;
    const uint32_t sW1 = sW0 + WBUFR;

    const int tile = blockIdx.x;      // 0..39 = b*5 + tq
    const int e    = blockIdx.y & 7;  // channel-eighth (128 ch)
    const int rr   = blockIdx.y >> 3; // ratio index
    const int b    = tile / 5;
    const int t0   = (tile - b*5) * 4;
    const int chb  = e * 128;
    const int ratio = rr + 1;

    const int tid  = threadIdx.x;
    const int wid  = tid >> 5, lane = tid & 31;
    const int mt   = wid;             // m16 tile = t row (t0+mt)

    // zero X buffers (invalid halo rows stay zero) + the zero block
    for (int i = tid; i < 2*XBUF/4; i += 128)
        ((uint32_t*)smem)[i] = 0;
    if (tid < 8)
        ((uint32_t*)(smem + ZOFF))[tid] = 0;

    // ---- X loader slots (5): 640 16B ops/chunk ----
    const __nv_bfloat16* xsrc[5];
    uint32_t xdst[5];
    #pragma unroll
    for (int k = 0; k < 5; k++) {
        int idx = tid + k*128;
        int h   = idx & 1;
        int mat = (idx >> 1) & 1;
        int row = idx >> 2;              // 0..159
        int tt = t0 + row/20 - 2, nn = row%20 - 2;
        xdst[k] = (uint32_t)(mat*XMAT + row*32 + h*16);
        xsrc[k] = (tt >= 0 && tt < TT && nn >= 0 && nn < TN)
                ? (mat ? g_xlo : g_xhi) + (size_t)((b*TT + tt)*TN + nn)*1024 + h*8
                : nullptr;
    }
    // ---- W loader slots (6): 648 16B ops/chunk (18 rows only) ----
    const __nv_bfloat16* wsrc[6];
    uint32_t wdst[6];
    #pragma unroll
    for (int k = 0; k < 6; k++) {
        int idx = tid + k*128;
        wsrc[k] = nullptr;
        if (idx < 648) {
            int h    = idx & 1;
            int row  = (idx >> 1) % 18;
            int mat  = (idx >> 1) / 18 % 2;
            int tap  = idx / 72;             // 0..8
            wdst[k] = (uint32_t)(((tap*2 + mat)*18 + row)*32 + h*16);
            wsrc[k] = (mat ? g_cwlo : g_cwhi)
                    + (size_t)((rr*9 + tap)*24 + row)*1024 + h*8;
        }
    }
    __syncthreads();

#define CT_ISSUE(ck, bX, bW) do { \
        int _c = chb + (ck)*16; \
        _Pragma("unroll") \
        for (int k = 0; k < 5; k++) \
            if (xsrc[k]) cp_async16((bX) + xdst[k], xsrc[k] + _c); \
        _Pragma("unroll") \
        for (int k = 0; k < 6; k++) \
            if (wsrc[k]) cp_async16((bW) + wdst[k], wsrc[k] + _c); \
        CP_COMMIT(); \
    } while (0)

    CT_ISSUE(0, sX0, sW0);

    float acc[3][4];
    #pragma unroll
    for (int nt = 0; nt < 3; nt++)
        #pragma unroll
        for (int q = 0; q < 4; q++) acc[nt][q] = 0.f;

    const uint32_t laneA = (uint32_t)((lane & 15)*32 + (lane >> 4)*16);
    const uint32_t hhalf = (uint32_t)(((lane >> 3) & 1) * 16);
    const uint32_t zad   = sb + ZOFF + hhalf;

    // per-nt B row offsets (within a (tap,mat) 18-row block); rows>=18 -> zero blk
    uint32_t roff[3];
    bool     rval[3];
    #pragma unroll
    for (int nt = 0; nt < 3; nt++) {
        int row = nt*8 + (lane & 7);
        rval[nt] = (row < 18);
        roff[nt] = (uint32_t)(row*32) + hhalf;
    }

    for (int ck = 0; ck < 8; ck++) {
        const uint32_t bX = (ck & 1) ? sX1 : sX0;
        const uint32_t bW = (ck & 1) ? sW1 : sW0;
        CP_WAIT0();
        __syncthreads();
        if (ck < 7) CT_ISSUE(ck + 1, (ck & 1) ? sX0 : sX1, (ck & 1) ? sW0 : sW1);

        #pragma unroll
        for (int tap = 0; tap < 9; tap++) {
            const int dt = tap/3 - 1, dn = tap%3 - 1;
            const int tp = mt + dt*ratio + 2;              // 0..7
            const uint32_t abase = bX + (uint32_t)((tp*20 + dn*ratio + 2)*32);
            uint32_t ah[4], al[4];
            LDM4(ah, abase + laneA);
            LDM4(al, abase + XMAT + laneA);
            const uint32_t wtap = bW + (uint32_t)(tap*1152);   // 2*18*32
            uint32_t bh[3][2], bl[3][2];
            #pragma unroll
            for (int nt = 0; nt < 3; nt++) {
                uint32_t hA = rval[nt] ? (wtap + roff[nt])        : zad;
                uint32_t lA = rval[nt] ? (wtap + 576u + roff[nt]) : zad;
                LDM2(bh[nt], hA);
                LDM2(bl[nt], lA);
            }
            // term-major: same-accumulator reuse distance = 3
            #pragma unroll
            for (int nt = 0; nt < 3; nt++) mma_bf16(acc[nt], ah, bh[nt]);
            #pragma unroll
            for (int nt = 0; nt < 3; nt++) mma_bf16(acc[nt], ah, bl[nt]);
            #pragma unroll
            for (int nt = 0; nt < 3; nt++) mma_bf16(acc[nt], al, bh[nt]);
        }
    }
#undef CT_ISSUE

    // epilogue: D rows = n-positions, cols = outputs (18 of 24 valid)
    const int r0 = lane >> 2;
    const int c0 = (lane & 3) * 2;
    const int posbase = b*320 + (t0 + mt)*16;
    #pragma unroll
    for (int nt = 0; nt < 3; nt++) {
        int o = nt*8 + c0;
        if (o < 18) {
            float* d0 = g_offp + ((size_t)(e*2 + rr)*NPOS + posbase + r0)*18 + o;
            float* d1 = g_offp + ((size_t)(e*2 + rr)*NPOS + posbase + r0 + 8)*18 + o;
            *(float2*)d0 = make_float2(acc[nt][0], acc[nt][1]);
            *(float2*)d1 = make_float2(acc[nt][2], acc[nt][3]);
        }
    }
}

// ---------------------------------------------------------------------------
// Kernel 3: deformable bilinear gather (R12 form; 16 partial slices).
// ---------------------------------------------------------------------------
__global__ void __launch_bounds__(256) k_gather(const float* __restrict__ x,
                                                const float* __restrict__ b1,
                                                const float* __restrict__ b2,
                                                float* __restrict__ out_ftmad,
                                                int write_ftmad) {
    int pos = blockIdx.x;
    int bb  = pos / 320; int rem = pos - bb*320;
    int t   = rem >> 4,  n = rem & 15;

    __shared__ int   s_off[2][9][4];
    __shared__ float s_coe[2][9][4];

    int tid = threadIdx.x;
    if (tid < 18) {
        int r = tid / 9, k = tid - r*9;
        int ratio = r + 1;
        const float* bias = r ? b2 : b1;
        float offt = bias[k], offn = bias[k + 9];
        #pragma unroll
        for (int q = 0; q < 8; q++) {
            const float* op = g_offp + ((size_t)(q*2 + r)*NPOS + pos)*18;
            offt += op[k];
            offn += op[k + 9];
        }
        float Tp1 = (float)(TT + 2*ratio - 1);
        float Np1 = (float)(TN + 2*ratio - 1);
        float post = (float)(t + ratio) + (float)((k/3 - 1)*ratio) + offt;
        float posn = (float)(n + ratio) + (float)((k%3 - 1)*ratio) + offn;
        float flt = floorf(post), fln = floorf(posn);
        float ltt = fminf(fmaxf(flt,       0.f), Tp1);
        float ltn = fminf(fmaxf(fln,       0.f), Np1);
        float rbt = fminf(fmaxf(flt + 1.f, 0.f), Tp1);
        float rbn = fminf(fmaxf(fln + 1.f, 0.f), Np1);
        float pct = fminf(fmaxf(post, 0.f), Tp1);
        float pcn = fminf(fmaxf(posn, 0.f), Np1);
        float wltt = 1.f - fabsf(pct - ltt);
        float wrbt = 1.f - fabsf(pct - rbt);
        float wltn = 1.f - fabsf(pcn - ltn);
        float wrbn = 1.f - fabsf(pcn - rbn);
        s_coe[r][k][0] = wltt * wltn;
        s_coe[r][k][1] = wrbt * wrbn;
        s_coe[r][k][2] = wrbt * wltn;
        s_coe[r][k][3] = wltt * wrbn;
        int ict[4] = {(int)ltt, (int)rbt, (int)rbt, (int)ltt};
        int icn[4] = {(int)ltn, (int)rbn, (int)ltn, (int)rbn};
        #pragma unroll
        for (int q = 0; q < 4; q++) {
            int ts = ict[q] - ratio, ns = icn[q] - ratio;
            s_off[r][k][q] = ((unsigned)ts < (unsigned)TT && (unsigned)ns < (unsigned)TN)
                           ? ((bb*TT + ts)*TN + ns)*TC : -1;
        }
    }
    __syncthreads();

    int c = tid * 4;
    float dx = 0.f, dy = 0.f, dz = 0.f, dw = 0.f;
    #pragma unroll
    for (int r = 0; r < 2; r++) {
        #pragma unroll
        for (int k = 0; k < 9; k++) {
            float fx = 0.f, fy = 0.f, fz = 0.f, fw = 0.f;
            #pragma unroll
            for (int q = 0; q < 4; q++) {
                int   o   = s_off[r][k][q];
                float coe = s_coe[r][k][q];
                if (o >= 0) {
                    float4 v = *(const float4*)(x + o + c);
                    fx = fmaf(coe, v.x, fx);
                    fy = fmaf(coe, v.y, fy);
                    fz = fmaf(coe, v.z, fz);
                    fw = fmaf(coe, v.w, fw);
                }
            }
            if (r == 1 && write_ftmad) {
                float4 ov = make_float4(fx, fy, fz, fw);
                *(float4*)(out_ftmad + (pos*9 + k)*1024 + c) = ov;
            }
            dx += fx; dy += fy; dz += fz; dw += fw;
        }
    }
    const float s = 1.f / 18.f;
    float4 dv = make_float4(dx*s, dy*s, dz*s, dw*s);

    BPack ph, pl;
    __nv_bfloat16 h;
    h = __float2bfloat16(dv.x); ph.h2[0].x = h; pl.h2[0].x = __float2bfloat16(dv.x - __bfloat162float(h));
    h = __float2bfloat16(dv.y); ph.h2[0].y = h; pl.h2[0].y = __float2bfloat16(dv.y - __bfloat162float(h));
    h = __float2bfloat16(dv.z); ph.h2[1].x = h; pl.h2[1].x = __float2bfloat16(dv.z - __bfloat162float(h));
    h = __float2bfloat16(dv.w); ph.h2[1].y = h; pl.h2[1].y = __float2bfloat16(dv.w - __bfloat162float(h));
    *(uint2*)(g_ahi + (long)pos*1024 + c) = ph.u;
    *(uint2*)(g_alo + (long)pos*1024 + c) = pl.u;
}

// ---------------------------------------------------------------------------
// Kernel 4: HMMA split GEMM v1c (R12 — known-good): M128xN64, 320 CTAs,
// occ 2, cp.async double-buffered, 1 sync per slab.
// ---------------------------------------------------------------------------
#define KC       32
#define NSLAB    (1024/KC)
#define SA       80
#define S_AHI    0
#define S_ALO    (128*SA)
#define S_BHI    (2*128*SA)
#define S_BLO    (2*128*SA + 64*SA)
#define STG      (2*128*SA + 2*64*SA)
#define GSMEM    (2*STG)

__global__ void __launch_bounds__(256, 2) k_gemm_mma(float* __restrict__ out) {
    extern __shared__ __align__(16) char smem[];
    const uint32_t sb = smem_u32(smem);

    const int tid  = threadIdx.x;
    const int wid  = tid >> 5;
    const int lane = tid & 31;
    const int bx   = blockIdx.x;      // N tile of 64 (0..15)
    const int by   = blockIdx.y;      // M tile of 128 (0..19)
    const int wy   = wid & 3;
    const int wx   = wid >> 2;

    const __nv_bfloat16* pAhi = g_ahi + (size_t)by*128*1024;
    const __nv_bfloat16* pAlo = g_alo + (size_t)by*128*1024;
    const __nv_bfloat16* pBhi = g_bhi + (size_t)bx*64*1024;
    const __nv_bfloat16* pBlo = g_blo + (size_t)bx*64*1024;

    const int lrow = tid >> 2, lc4 = tid & 3;
    const size_t ga0 = (size_t)lrow*1024 + lc4*8;
    const size_t ga1 = (size_t)(lrow+64)*1024 + lc4*8;
    const uint32_t sa0 = (uint32_t)(lrow*SA + lc4*16);
    const uint32_t sa1 = (uint32_t)((lrow+64)*SA + lc4*16);

    float acc[2][4][4];
    #pragma unroll
    for (int i = 0; i < 2; i++)
        #pragma unroll
        for (int j = 0; j < 4; j++)
            #pragma unroll
            for (int q = 0; q < 4; q++) acc[i][j][q] = 0.f;

    const uint32_t laneA = (uint32_t)((lane & 15)*SA + (lane >> 4)*16);
    const uint32_t laneB = (uint32_t)((lane & 7)*SA + ((lane >> 3) & 1)*16);

#define GEMM_ISSUE(k0, bufbase) do { \
        cp_async16((bufbase) + S_AHI + sa0, pAhi + ga0 + (k0)); \
        cp_async16((bufbase) + S_AHI + sa1, pAhi + ga1 + (k0)); \
        cp_async16((bufbase) + S_ALO + sa0, pAlo + ga0 + (k0)); \
        cp_async16((bufbase) + S_ALO + sa1, pAlo + ga1 + (k0)); \
        cp_async16((bufbase) + S_BHI + sa0, pBhi + ga0 + (k0)); \
        cp_async16((bufbase) + S_BLO + sa0, pBlo + ga0 + (k0)); \
        CP_COMMIT(); \
    } while (0)

    GEMM_ISSUE(0, sb);

    for (int s = 0; s < NSLAB; s++) {
        const uint32_t base = sb + (uint32_t)(s & 1)*STG;
        CP_WAIT0();
        __syncthreads();
        if (s + 1 < NSLAB)
            GEMM_ISSUE((size_t)(s + 1)*KC, sb + (uint32_t)((s + 1) & 1)*STG);

        #pragma unroll
        for (int kk = 0; kk < 2; kk++) {
            uint32_t kB = kk * 32;
            uint32_t ah[2][4], al[2][4], bh[4][2], bl[4][2];
            #pragma unroll
            for (int mi = 0; mi < 2; mi++) {
                uint32_t moff = (uint32_t)((wy*32 + mi*16)*SA) + kB + laneA;
                LDM4(ah[mi], base + S_AHI + moff);
                LDM4(al[mi], base + S_ALO + moff);
            }
            #pragma unroll
            for (int ni = 0; ni < 4; ni++) {
                uint32_t noff = (uint32_t)((wx*32 + ni*8)*SA) + kB + laneB;
                LDM2(bh[ni], base + S_BHI + noff);
                LDM2(bl[ni], base + S_BLO + noff);
            }
            #pragma unroll
            for (int mi = 0; mi < 2; mi++)
                #pragma unroll
                for (int ni = 0; ni < 4; ni++) {
                    mma_bf16(acc[mi][ni], ah[mi], bh[ni]);
                    mma_bf16(acc[mi][ni], ah[mi], bl[ni]);
                    mma_bf16(acc[mi][ni], al[mi], bh[ni]);
                }
        }
    }
#undef GEMM_ISSUE

    const int r0 = (lane >> 2);
    const int c0 = (lane & 3) * 2;
    #pragma unroll
    for (int mi = 0; mi < 2; mi++) {
        #pragma unroll
        for (int ni = 0; ni < 4; ni++) {
            size_t row = (size_t)by*128 + wy*32 + mi*16 + r0;
            size_t col = (size_t)bx*64 + wx*32 + ni*8 + c0;
            *(float2*)(out + row*1024 + col)       = make_float2(acc[mi][ni][0], acc[mi][ni][1]);
            *(float2*)(out + (row + 8)*1024 + col) = make_float2(acc[mi][ni][2], acc[mi][ni][3]);
        }
    }
}

// ---------------------------------------------------------------------------
extern "C" void kernel_launch(void* const* d_in, const int* in_sizes, int n_in,
                              void* d_out, int out_size) {
    const float* xf  = (const float*)d_in[0];  // person_features [8,20,16,1024]
    const float* Wh  = (const float*)d_in[1];  // W_hidden [1024,1024]
    const float* w1  = (const float*)d_in[2];  // p_w1 [18,1024,3,3]
    const float* bb1 = (const float*)d_in[3];  // p_b1 [18]
    const float* w2  = (const float*)d_in[4];  // p_w2 [18,1024,3,3]
    const float* bb2 = (const float*)d_in[5];  // p_b2 [18]
    (void)in_sizes; (void)n_in;

    float* out       = (float*)d_out;
    float* out_dyn   = out;                       // [2560,1024]
    float* out_ftmad = out + (long)NPOS * TC;     // [2560,9,1024]
    int write_ftmad  = (out_size >= NPOS*TC + NPOS*9*TC) ? 1 : 0;

    cudaFuncSetAttribute(k_gemm_mma, cudaFuncAttributeMaxDynamicSharedMemorySize,
                         GSMEM);
    cudaFuncSetAttribute(k_conv_tc, cudaFuncAttributeMaxDynamicSharedMemorySize,
                         CT_SMEM);

    k_cwprep<<<(2*9*24*1024 + 255)/256, 256>>>(w1, w2);
    k_xprep<<<NPOS, 256>>>(xf);
    k_wprep<<<1024, 256>>>(Wh);

    dim3 gconv(40, 16);
    k_conv_tc<<<gconv, 128, CT_SMEM>>>();

    k_gather<<<NPOS, 256>>>(xf, bb1, bb2, out_ftmad, write_ftmad);

    dim3 ggemm(16, 20);
    k_gemm_mma<<<ggemm, 256, GSMEM>>>(out_dyn);
}